// round 7
// baseline (speedup 1.0000x reference)
#include <cuda_runtime.h>
#include <cuda_bf16.h>
#include <math.h>

#define NN   384
#define EE   3456
#define ENS  3072
#define F3   64
#define KK   32
#define NLAY 6

__device__ float g_h[2][NLAY][NN][F3];
__device__ float g_hcur[2][NN][F3];
__device__ float g_agg[2][NN][F3];
__device__ float g_z[2][NN][F3];
__device__ float g_deg[2][NN];
__device__ float g_AT[NLAY][NN][F3][KK];   // A transposed: [l][i][e][k]
__device__ float g_h2T[NLAY][F3][NN];
__device__ float g_pat[NN][NN][KK];

// ---------------- degrees: distinct dst per src over first 3072 edges -------
__global__ void k_deg(const int* __restrict__ e1, const int* __restrict__ e2) {
    __shared__ unsigned smask[4][12];
    int g = blockIdx.y;
    const int* E = g ? e2 : e1;
    int wid = threadIdx.x >> 5, lane = threadIdx.x & 31;
    int node = blockIdx.x * 4 + wid;
    if (lane < 12) smask[wid][lane] = 0u;
    __syncwarp();
    for (int t = lane; t < ENS; t += 32) {
        if (E[t] == node) {
            int d = E[EE + t];
            atomicOr(&smask[wid][d >> 5], 1u << (d & 31));
        }
    }
    __syncwarp();
    unsigned m = (lane < 12) ? smask[wid][lane] : 0u;
    int cnt = __popc(m);
#pragma unroll
    for (int o = 16; o; o >>= 1) cnt += __shfl_xor_sync(0xffffffffu, cnt, o);
    if (lane == 0) g_deg[g][node] = (float)cnt;
}

// ---------------- lin0 ------------------------------------------------------
__global__ void k_lin0(const float* __restrict__ f1, const float* __restrict__ f2,
                       const float* __restrict__ w1, const float* __restrict__ b1,
                       const float* __restrict__ w2, const float* __restrict__ b2) {
    int g = blockIdx.y, rt = blockIdx.x;
    const float* F = g ? f2 : f1;
    __shared__ float xs[64][33];
    __shared__ float w1s[33 * 64];
    __shared__ float hid[64 * 64];
    int tid = threadIdx.x;
    for (int idx = tid; idx < 33 * 64; idx += 256) w1s[idx] = w1[idx];
    for (int idx = tid; idx < 64 * 32; idx += 256) xs[idx >> 5][idx & 31] = F[rt * 2048 + idx];
    if (tid < 64) xs[tid][32] = g_deg[g][rt * 64 + tid];
    for (int idx = tid; idx < 64 * 64; idx += 256)
        g_agg[g][rt * 64 + (idx >> 6)][idx & 63] = 0.f;
    __syncthreads();
    int c = tid & 63, r0 = tid >> 6;
#pragma unroll 1
    for (int rr = 0; rr < 16; rr++) {
        int r = r0 + rr * 4;
        float acc = b1[c];
#pragma unroll
        for (int d = 0; d < 33; d++) acc += xs[r][d] * w1s[d * 64 + c];
        hid[r * 64 + c] = fmaxf(acc, 0.f);
    }
    __syncthreads();
#pragma unroll 1
    for (int rr = 0; rr < 16; rr++) {
        int r = r0 + rr * 4;
        float acc = b2[c];
#pragma unroll
        for (int m = 0; m < 64; m++) acc += hid[r * 64 + m] * w2[m * 64 + c];
        int row = rt * 64 + r;
        g_h[g][0][row][c] = acc;
        g_hcur[g][row][c] = acc;   // first GIN consumes h0 WITHOUT relu
    }
}

// ---------------- GIN aggregation ------------------------------------------
__global__ void k_agg(const int* __restrict__ e1, const int* __restrict__ e2) {
    int idx = blockIdx.x * 256 + threadIdx.x;          // 2*3456*64 threads
    int c = idx & 63;
    int e = (idx >> 6) % EE;
    int g = idx / (EE * 64);
    const int* E = g ? e2 : e1;
    atomicAdd(&g_agg[g][E[EE + e]][c], g_hcur[g][E[e]][c]);
}

// ---------------- GIN MLP ---------------------------------------------------
__global__ void k_mlp(const float* __restrict__ gw1, const float* __restrict__ gb1,
                      const float* __restrict__ gw2, const float* __restrict__ gb2,
                      const float* __restrict__ geps, int l) {
    int g = blockIdx.y, rt = blockIdx.x;
    __shared__ float zs[64][64];
    __shared__ float ws[64 * 64];
    __shared__ float hid[64 * 64];
    int tid = threadIdx.x;
    float eps1 = 1.f + geps[l];
    const float* w1 = gw1 + l * 4096;
    const float* w2 = gw2 + l * 4096;
    for (int idx = tid; idx < 4096; idx += 256) ws[idx] = w1[idx];
    for (int idx = tid; idx < 4096; idx += 256) {
        int r = idx >> 6, d = idx & 63, row = rt * 64 + r;
        zs[r][d] = eps1 * g_hcur[g][row][d] + g_agg[g][row][d];
    }
    __syncthreads();
    int c = tid & 63, r0 = tid >> 6;
#pragma unroll 1
    for (int rr = 0; rr < 16; rr++) {
        int r = r0 + rr * 4;
        float acc = gb1[l * 64 + c];
#pragma unroll
        for (int d = 0; d < 64; d++) acc += zs[r][d] * ws[d * 64 + c];
        hid[r * 64 + c] = fmaxf(acc, 0.f);
    }
    __syncthreads();
#pragma unroll 1
    for (int rr = 0; rr < 16; rr++) {
        int r = r0 + rr * 4;
        float acc = gb2[l * 64 + c];
#pragma unroll
        for (int m = 0; m < 64; m++) acc += hid[r * 64 + m] * w2[m * 64 + c];
        g_z[g][rt * 64 + r][c] = acc;
    }
}

// ---------------- BatchNorm + relu + zero agg -------------------------------
__global__ void k_bn(const float* __restrict__ gamma, const float* __restrict__ beta, int l) {
    int c = blockIdx.x, g = blockIdx.y, t = threadIdx.x;   // 384 threads
    __shared__ float red[12];
    __shared__ float bc;
    float val = g_z[g][t][c];
    float s = val;
#pragma unroll
    for (int o = 16; o; o >>= 1) s += __shfl_xor_sync(0xffffffffu, s, o);
    if ((t & 31) == 0) red[t >> 5] = s;
    __syncthreads();
    if (t < 32) {
        float v = (t < 12) ? red[t] : 0.f;
#pragma unroll
        for (int o = 16; o; o >>= 1) v += __shfl_xor_sync(0xffffffffu, v, o);
        if (t == 0) bc = v * (1.f / 384.f);
    }
    __syncthreads();
    float mu = bc;
    __syncthreads();
    float d = val - mu;
    float s2 = d * d;
#pragma unroll
    for (int o = 16; o; o >>= 1) s2 += __shfl_xor_sync(0xffffffffu, s2, o);
    if ((t & 31) == 0) red[t >> 5] = s2;
    __syncthreads();
    if (t < 32) {
        float v = (t < 12) ? red[t] : 0.f;
#pragma unroll
        for (int o = 16; o; o >>= 1) v += __shfl_xor_sync(0xffffffffu, v, o);
        if (t == 0) bc = v * (1.f / 384.f);
    }
    __syncthreads();
    float var = bc;
    float norm = d * rsqrtf(var + 1e-5f) * gamma[l * 64 + c] + beta[l * 64 + c];
    g_h[g][l + 1][t][c] = norm;
    g_hcur[g][t][c] = fmaxf(norm, 0.f);
    g_agg[g][t][c] = 0.f;
}

// ---------------- A^T[l,i,e,k] = sum_d h1[l,i,d]*ged[l,k,d,e] ---------------
// No per-thread arrays: 16 accumulators as 4 named float4s.
__global__ void k_A(const float* __restrict__ ged) {
    int l = blockIdx.x, it = blockIdx.y * 16;
    __shared__ float h1s[16][64];
    int tid = threadIdx.x;
    for (int idx = tid; idx < 1024; idx += 256)
        h1s[idx >> 6][idx & 63] = g_h[0][l][it + (idx >> 6)][idx & 63];
    __syncthreads();
    int e = tid & 63, kq = tid >> 6;
#pragma unroll 1
    for (int kk2 = 0; kk2 < 8; kk2++) {
        int k = kq * 8 + kk2;
        float4 a0 = make_float4(0.f, 0.f, 0.f, 0.f);
        float4 a1 = make_float4(0.f, 0.f, 0.f, 0.f);
        float4 a2 = make_float4(0.f, 0.f, 0.f, 0.f);
        float4 a3 = make_float4(0.f, 0.f, 0.f, 0.f);
        const float* mp = ged + ((l * KK + k) * 64) * 64 + e;
#pragma unroll 4
        for (int d = 0; d < 64; d++) {
            float m = mp[d * 64];
            a0.x += h1s[0][d] * m;  a0.y += h1s[1][d] * m;
            a0.z += h1s[2][d] * m;  a0.w += h1s[3][d] * m;
            a1.x += h1s[4][d] * m;  a1.y += h1s[5][d] * m;
            a1.z += h1s[6][d] * m;  a1.w += h1s[7][d] * m;
            a2.x += h1s[8][d] * m;  a2.y += h1s[9][d] * m;
            a2.z += h1s[10][d] * m; a2.w += h1s[11][d] * m;
            a3.x += h1s[12][d] * m; a3.y += h1s[13][d] * m;
            a3.z += h1s[14][d] * m; a3.w += h1s[15][d] * m;
        }
        g_AT[l][it + 0][e][k]  = a0.x;  g_AT[l][it + 1][e][k]  = a0.y;
        g_AT[l][it + 2][e][k]  = a0.z;  g_AT[l][it + 3][e][k]  = a0.w;
        g_AT[l][it + 4][e][k]  = a1.x;  g_AT[l][it + 5][e][k]  = a1.y;
        g_AT[l][it + 6][e][k]  = a1.z;  g_AT[l][it + 7][e][k]  = a1.w;
        g_AT[l][it + 8][e][k]  = a2.x;  g_AT[l][it + 9][e][k]  = a2.y;
        g_AT[l][it + 10][e][k] = a2.z;  g_AT[l][it + 11][e][k] = a2.w;
        g_AT[l][it + 12][e][k] = a3.x;  g_AT[l][it + 13][e][k] = a3.y;
        g_AT[l][it + 14][e][k] = a3.z;  g_AT[l][it + 15][e][k] = a3.w;
    }
}

// ---------------- transpose h2 ----------------------------------------------
__global__ void k_h2T() {
    int idx = blockIdx.x * 256 + threadIdx.x;
    if (idx >= NLAY * 64 * NN) return;
    int l = idx / (64 * NN), rem = idx % (64 * NN);
    int e = rem / NN, j = rem % NN;
    g_h2T[l][e][j] = g_h[1][l][j][e];
}

// ---------------- float4 helpers (structs only; no arrays) ------------------
__device__ __forceinline__ float4 shfl4(float4 v, int s) {
    float4 r;
    r.x = __shfl_sync(0xffffffffu, v.x, s);
    r.y = __shfl_sync(0xffffffffu, v.y, s);
    r.z = __shfl_sync(0xffffffffu, v.z, s);
    r.w = __shfl_sync(0xffffffffu, v.w, s);
    return r;
}
__device__ __forceinline__ float sigm_f(float x) { return 1.f / (1.f + __expf(-x)); }
__device__ __forceinline__ float tanh_f(float x) { return 1.f - 2.f / (1.f + __expf(2.f * x)); }
__device__ __forceinline__ float4 set4(float v) { return make_float4(v, v, v, v); }

// ---------------- phase 1: GRU + layer attention -> g_pat -------------------
// lane = channel k; warp = 4 pairs (j0..j0+3) held in float4 components.
__global__ void __launch_bounds__(256)
k_pat(const float* __restrict__ wih, const float* __restrict__ whh,
      const float* __restrict__ bih, const float* __restrict__ bhh,
      const float* __restrict__ wattn, const float* __restrict__ wattnb,
      const float* __restrict__ vattn) {
    __shared__ float s_AT[2048];       // [e*32+k] for current layer
    __shared__ float s_wih[3072];      // [m*96+c] (transposed)
    __shared__ float s_whh[3072];
    __shared__ float s_wa[1024];       // wattn [m*32+kp] direct

    int tid = threadIdx.x, i = blockIdx.x, jb = blockIdx.y;
    int w = tid >> 5, k = tid & 31;
    int j0 = jb * 32 + w * 4;

    for (int idx = tid; idx < 3072; idx += 256) {
        int m = idx / 96, c = idx - m * 96;
        s_wih[idx] = wih[c * 32 + m];
        s_whh[idx] = whh[c * 32 + m];
    }
    for (int idx = tid; idx < 1024; idx += 256) s_wa[idx] = wattn[idx];

    float bihr = bih[k], bihz = bih[32 + k], bihn = bih[64 + k];
    float bhhr = bhh[k], bhhz = bhh[32 + k], bhhn = bhh[64 + k];
    float wabk = wattnb[k], vk = vattn[k];

    float4 h4 = set4(0.f), pacc = set4(0.f);
    float4 M4 = set4(-1e30f), S4 = set4(0.f);

#pragma unroll 1
    for (int l = 0; l < 6; l++) {
        __syncthreads();
        const float* src = &g_AT[l][i][0][0];
        for (int idx = tid; idx < 2048; idx += 256) s_AT[idx] = src[idx];
        __syncthreads();

        // x_k = sum_e A[k][e] * h2[e][j]  (4 pairs)
        const float* h2b = &g_h2T[l][0][0];
        float4 h2lo = *(const float4*)(h2b + k * NN + j0);
        float4 h2hi = *(const float4*)(h2b + (32 + k) * NN + j0);
        float4 x4 = set4(0.f);
#pragma unroll 4
        for (int e = 0; e < 32; e++) {
            float4 v = shfl4(h2lo, e);
            float a = s_AT[e * 32 + k];
            x4.x += a * v.x; x4.y += a * v.y; x4.z += a * v.z; x4.w += a * v.w;
            float4 v2 = shfl4(h2hi, e);
            float a2 = s_AT[(32 + e) * 32 + k];
            x4.x += a2 * v2.x; x4.y += a2 * v2.y; x4.z += a2 * v2.z; x4.w += a2 * v2.w;
        }

        // GRU gates via shuffle-broadcast of x and h
        float4 air = set4(bihr), aiz = set4(bihz), ain = set4(bihn);
        float4 ahr = set4(bhhr), ahz = set4(bhhz), ahn = set4(bhhn);
#pragma unroll 4
        for (int m = 0; m < 32; m++) {
            float4 xm = shfl4(x4, m);
            float4 hm = shfl4(h4, m);
            float wir = s_wih[m * 96 + k], wiz = s_wih[m * 96 + 32 + k], win = s_wih[m * 96 + 64 + k];
            float whr = s_whh[m * 96 + k], whz = s_whh[m * 96 + 32 + k], whn = s_whh[m * 96 + 64 + k];
            air.x += wir * xm.x; air.y += wir * xm.y; air.z += wir * xm.z; air.w += wir * xm.w;
            aiz.x += wiz * xm.x; aiz.y += wiz * xm.y; aiz.z += wiz * xm.z; aiz.w += wiz * xm.w;
            ain.x += win * xm.x; ain.y += win * xm.y; ain.z += win * xm.z; ain.w += win * xm.w;
            ahr.x += whr * hm.x; ahr.y += whr * hm.y; ahr.z += whr * hm.z; ahr.w += whr * hm.w;
            ahz.x += whz * hm.x; ahz.y += whz * hm.y; ahz.z += whz * hm.z; ahz.w += whz * hm.w;
            ahn.x += whn * hm.x; ahn.y += whn * hm.y; ahn.z += whn * hm.z; ahn.w += whn * hm.w;
        }
        float rx = sigm_f(air.x + ahr.x), ry = sigm_f(air.y + ahr.y);
        float rz = sigm_f(air.z + ahr.z), rw = sigm_f(air.w + ahr.w);
        float zx = sigm_f(aiz.x + ahz.x), zy = sigm_f(aiz.y + ahz.y);
        float zz = sigm_f(aiz.z + ahz.z), zw = sigm_f(aiz.w + ahz.w);
        float nx = tanh_f(ain.x + rx * ahn.x), ny = tanh_f(ain.y + ry * ahn.y);
        float nz = tanh_f(ain.z + rz * ahn.z), nw = tanh_f(ain.w + rw * ahn.w);
        h4.x = (1.f - zx) * nx + zx * h4.x;
        h4.y = (1.f - zy) * ny + zy * h4.y;
        h4.z = (1.f - zz) * nz + zz * h4.z;
        h4.w = (1.f - zw) * nw + zw * h4.w;

        // attention score: sc_j = sum_kp tanh(wab+wattn·h)_kp * v_kp
        float4 t4 = set4(wabk);
#pragma unroll 4
        for (int m = 0; m < 32; m++) {
            float4 hm = shfl4(h4, m);
            float wv_ = s_wa[m * 32 + k];
            t4.x += wv_ * hm.x; t4.y += wv_ * hm.y; t4.z += wv_ * hm.z; t4.w += wv_ * hm.w;
        }
        t4.x = tanh_f(t4.x) * vk; t4.y = tanh_f(t4.y) * vk;
        t4.z = tanh_f(t4.z) * vk; t4.w = tanh_f(t4.w) * vk;
#pragma unroll
        for (int o = 16; o; o >>= 1) {
            t4.x += __shfl_xor_sync(0xffffffffu, t4.x, o);
            t4.y += __shfl_xor_sync(0xffffffffu, t4.y, o);
            t4.z += __shfl_xor_sync(0xffffffffu, t4.z, o);
            t4.w += __shfl_xor_sync(0xffffffffu, t4.w, o);
        }
        // online softmax over layers, per pair component
        float4 nm4;
        nm4.x = fmaxf(M4.x, t4.x); nm4.y = fmaxf(M4.y, t4.y);
        nm4.z = fmaxf(M4.z, t4.z); nm4.w = fmaxf(M4.w, t4.w);
        float f0x = __expf(M4.x - nm4.x), f0y = __expf(M4.y - nm4.y);
        float f0z = __expf(M4.z - nm4.z), f0w = __expf(M4.w - nm4.w);
        float px = __expf(t4.x - nm4.x), py = __expf(t4.y - nm4.y);
        float pz = __expf(t4.z - nm4.z), pw = __expf(t4.w - nm4.w);
        S4.x = S4.x * f0x + px; S4.y = S4.y * f0y + py;
        S4.z = S4.z * f0z + pz; S4.w = S4.w * f0w + pw;
        pacc.x = pacc.x * f0x + px * h4.x;
        pacc.y = pacc.y * f0y + py * h4.y;
        pacc.z = pacc.z * f0z + pz * h4.z;
        pacc.w = pacc.w * f0w + pw * h4.w;
        M4 = nm4;
    }
    g_pat[i][j0 + 0][k] = pacc.x / S4.x;
    g_pat[i][j0 + 1][k] = pacc.y / S4.y;
    g_pat[i][j0 + 2][k] = pacc.z / S4.z;
    g_pat[i][j0 + 3][k] = pacc.w / S4.w;
}

// ---------------- phase 2: q/k/v + layer softmax -> context -----------------
__global__ void __launch_bounds__(256)
k_ctx(const float* __restrict__ wq1, const float* __restrict__ wq1b,
      const float* __restrict__ wq2, const float* __restrict__ wq2b,
      const float* __restrict__ wk, const float* __restrict__ wkb,
      const float* __restrict__ wv, const float* __restrict__ wvb,
      float* __restrict__ out) {
    __shared__ float s_AT[2048];
    __shared__ float s_wq1[1024];      // [m*32+kp] direct
    __shared__ float s_wq2[1024];
    __shared__ float s_wkT[1024];      // [p*32+e] (transposed)
    __shared__ float s_wv[1024];       // [p*32+k] direct

    int tid = threadIdx.x, i = blockIdx.x, jb = blockIdx.y;
    int w = tid >> 5, k = tid & 31;
    int j0 = jb * 32 + w * 4;

    for (int idx = tid; idx < 1024; idx += 256) {
        int p = idx >> 5, e = idx & 31;
        s_wq1[idx] = wq1[idx];
        s_wq2[idx] = wq2[idx];
        s_wv[idx]  = wv[idx];
        s_wkT[idx] = wk[e * 32 + p];
    }
    float wq1bk = wq1b[k], wq2bk = wq2b[k], wkbk = wkb[k], wvbk = wvb[k];
    __syncthreads();

    // pattern -> t1 -> q -> qk (= wk^T applied), qbk (= q.bk)
    float4 pat;
    pat.x = g_pat[i][j0 + 0][k];
    pat.y = g_pat[i][j0 + 1][k];
    pat.z = g_pat[i][j0 + 2][k];
    pat.w = g_pat[i][j0 + 3][k];

    float4 t1 = set4(wq1bk);
#pragma unroll 4
    for (int m = 0; m < 32; m++) {
        float4 pm = shfl4(pat, m);
        float wv_ = s_wq1[m * 32 + k];
        t1.x += wv_ * pm.x; t1.y += wv_ * pm.y; t1.z += wv_ * pm.z; t1.w += wv_ * pm.w;
    }
    t1.x = fmaxf(t1.x, 0.f); t1.y = fmaxf(t1.y, 0.f);
    t1.z = fmaxf(t1.z, 0.f); t1.w = fmaxf(t1.w, 0.f);

    float4 q4 = set4(wq2bk);
#pragma unroll 4
    for (int m = 0; m < 32; m++) {
        float4 tm = shfl4(t1, m);
        float wv_ = s_wq2[m * 32 + k];
        q4.x += wv_ * tm.x; q4.y += wv_ * tm.y; q4.z += wv_ * tm.z; q4.w += wv_ * tm.w;
    }

    float4 qk4 = set4(0.f);        // qk_e = sum_p wk[e][p] q_p ; lane = e
#pragma unroll 4
    for (int p = 0; p < 32; p++) {
        float4 qm = shfl4(q4, p);
        float wv_ = s_wkT[p * 32 + k];
        qk4.x += wv_ * qm.x; qk4.y += wv_ * qm.y; qk4.z += wv_ * qm.z; qk4.w += wv_ * qm.w;
    }
    float4 qb4;
    qb4.x = q4.x * wkbk; qb4.y = q4.y * wkbk; qb4.z = q4.z * wkbk; qb4.w = q4.w * wkbk;
#pragma unroll
    for (int o = 16; o; o >>= 1) {
        qb4.x += __shfl_xor_sync(0xffffffffu, qb4.x, o);
        qb4.y += __shfl_xor_sync(0xffffffffu, qb4.y, o);
        qb4.z += __shfl_xor_sync(0xffffffffu, qb4.z, o);
        qb4.w += __shfl_xor_sync(0xffffffffu, qb4.w, o);
    }

    float4 sacc = set4(0.f), M4 = set4(-1e30f), S4 = set4(0.f);
#pragma unroll 1
    for (int l = 0; l < 6; l++) {
        __syncthreads();
        const float* src = &g_AT[l][i][0][0];
        for (int idx = tid; idx < 2048; idx += 256) s_AT[idx] = src[idx];
        __syncthreads();

        const float* h2b = &g_h2T[l][0][0];
        float4 h2lo = *(const float4*)(h2b + k * NN + j0);
        float4 h2hi = *(const float4*)(h2b + (32 + k) * NN + j0);
        float4 x4 = set4(0.f);
#pragma unroll 4
        for (int e = 0; e < 32; e++) {
            float4 v = shfl4(h2lo, e);
            float a = s_AT[e * 32 + k];
            x4.x += a * v.x; x4.y += a * v.y; x4.z += a * v.z; x4.w += a * v.w;
            float4 v2 = shfl4(h2hi, e);
            float a2 = s_AT[(32 + e) * 32 + k];
            x4.x += a2 * v2.x; x4.y += a2 * v2.y; x4.z += a2 * v2.z; x4.w += a2 * v2.w;
        }

        // s_j = (qbk + sum_e qk_e x_e) / sqrt(K)
        float4 s4;
        s4.x = qk4.x * x4.x; s4.y = qk4.y * x4.y; s4.z = qk4.z * x4.z; s4.w = qk4.w * x4.w;
#pragma unroll
        for (int o = 16; o; o >>= 1) {
            s4.x += __shfl_xor_sync(0xffffffffu, s4.x, o);
            s4.y += __shfl_xor_sync(0xffffffffu, s4.y, o);
            s4.z += __shfl_xor_sync(0xffffffffu, s4.z, o);
            s4.w += __shfl_xor_sync(0xffffffffu, s4.w, o);
        }
        s4.x = (s4.x + qb4.x) * 0.17677669529663687f;
        s4.y = (s4.y + qb4.y) * 0.17677669529663687f;
        s4.z = (s4.z + qb4.z) * 0.17677669529663687f;
        s4.w = (s4.w + qb4.w) * 0.17677669529663687f;

        float4 nm4;
        nm4.x = fmaxf(M4.x, s4.x); nm4.y = fmaxf(M4.y, s4.y);
        nm4.z = fmaxf(M4.z, s4.z); nm4.w = fmaxf(M4.w, s4.w);
        float f0x = __expf(M4.x - nm4.x), f0y = __expf(M4.y - nm4.y);
        float f0z = __expf(M4.z - nm4.z), f0w = __expf(M4.w - nm4.w);
        float px = __expf(s4.x - nm4.x), py = __expf(s4.y - nm4.y);
        float pz = __expf(s4.z - nm4.z), pw = __expf(s4.w - nm4.w);
        S4.x = S4.x * f0x + px; S4.y = S4.y * f0y + py;
        S4.z = S4.z * f0z + pz; S4.w = S4.w * f0w + pw;
        sacc.x = sacc.x * f0x + px * x4.x;
        sacc.y = sacc.y * f0y + py * x4.y;
        sacc.z = sacc.z * f0z + pz * x4.z;
        sacc.w = sacc.w * f0w + pw * x4.w;
        M4 = nm4;
    }
    sacc.x /= S4.x; sacc.y /= S4.y; sacc.z /= S4.z; sacc.w /= S4.w;

    // context_k = wvb_k + sum_p wv[p][k] sacc_p
    float4 c4 = set4(wvbk);
#pragma unroll 4
    for (int p = 0; p < 32; p++) {
        float4 sm4 = shfl4(sacc, p);
        float wv_ = s_wv[p * 32 + k];
        c4.x += wv_ * sm4.x; c4.y += wv_ * sm4.y; c4.z += wv_ * sm4.z; c4.w += wv_ * sm4.w;
    }
    out[((size_t)i * NN + j0 + 0) * KK + k] = c4.x;
    out[((size_t)i * NN + j0 + 1) * KK + k] = c4.y;
    out[((size_t)i * NN + j0 + 2) * KK + k] = c4.z;
    out[((size_t)i * NN + j0 + 3) * KK + k] = c4.w;
}

// ---------------- host ------------------------------------------------------
extern "C" void kernel_launch(void* const* d_in, const int* in_sizes, int n_in,
                              void* d_out, int out_size) {
    const float* f1   = (const float*)d_in[0];
    const float* f2   = (const float*)d_in[1];
    const float* l0w1 = (const float*)d_in[2];
    const float* l0b1 = (const float*)d_in[3];
    const float* l0w2 = (const float*)d_in[4];
    const float* l0b2 = (const float*)d_in[5];
    const float* geps = (const float*)d_in[6];
    const float* gw1  = (const float*)d_in[7];
    const float* gb1  = (const float*)d_in[8];
    const float* gw2  = (const float*)d_in[9];
    const float* gb2  = (const float*)d_in[10];
    const float* gga  = (const float*)d_in[11];
    const float* gbe  = (const float*)d_in[12];
    const float* ged  = (const float*)d_in[13];
    const float* wih  = (const float*)d_in[14];
    const float* whh  = (const float*)d_in[15];
    const float* bih  = (const float*)d_in[16];
    const float* bhh  = (const float*)d_in[17];
    const float* waw  = (const float*)d_in[18];
    const float* wab  = (const float*)d_in[19];
    const float* vat  = (const float*)d_in[20];
    const float* wq1  = (const float*)d_in[21];
    const float* wq1b = (const float*)d_in[22];
    const float* wq2  = (const float*)d_in[23];
    const float* wq2b = (const float*)d_in[24];
    const float* wk   = (const float*)d_in[25];
    const float* wkb  = (const float*)d_in[26];
    const float* wv   = (const float*)d_in[27];
    const float* wvb  = (const float*)d_in[28];
    const int*   e1   = (const int*)d_in[29];
    const int*   e2   = (const int*)d_in[30];
    float* out = (float*)d_out;

    k_deg<<<dim3(96, 2), 128>>>(e1, e2);
    k_lin0<<<dim3(6, 2), 256>>>(f1, f2, l0w1, l0b1, l0w2, l0b2);
    for (int l = 0; l < 5; l++) {
        k_agg<<<1728, 256>>>(e1, e2);
        k_mlp<<<dim3(6, 2), 256>>>(gw1, gb1, gw2, gb2, geps, l);
        k_bn<<<dim3(64, 2), 384>>>(gga, gbe, l);
    }
    k_A<<<dim3(6, 24), 256>>>(ged);
    k_h2T<<<576, 256>>>();
    k_pat<<<dim3(384, 12), 256>>>(wih, whh, bih, bhh, waw, wab, vat);
    k_ctx<<<dim3(384, 12), 256>>>(wq1, wq1b, wq2, wq2b, wk, wkb, wv, wvb, out);
}

// round 9
// speedup vs baseline: 1.2402x; 1.2402x over previous
#include <cuda_runtime.h>
#include <cuda_bf16.h>
#include <math.h>

#define NN   384
#define EE   3456
#define ENS  3072
#define F3   64
#define KK   32
#define NLAY 6

__device__ float g_h[2][NLAY][NN][F3];
__device__ float g_hcur[2][NN][F3];
__device__ float g_agg[2][NN][F3];
__device__ float g_z[2][NN][F3];
__device__ float g_deg[2][NN];
__device__ float g_AT[NLAY][NN][F3][KK];   // A transposed: [l][i][e][k]
__device__ float g_h2T[NLAY][F3][NN];
__device__ float g_pat[NN][NN][KK];
__device__ float g_X[NLAY][NN][NN][KK];    // stack values, written by k_pat

// ---------------- degrees: distinct dst per src over first 3072 edges -------
__global__ void k_deg(const int* __restrict__ e1, const int* __restrict__ e2) {
    __shared__ unsigned smask[4][12];
    int g = blockIdx.y;
    const int* E = g ? e2 : e1;
    int wid = threadIdx.x >> 5, lane = threadIdx.x & 31;
    int node = blockIdx.x * 4 + wid;
    if (lane < 12) smask[wid][lane] = 0u;
    __syncwarp();
    for (int t = lane; t < ENS; t += 32) {
        if (E[t] == node) {
            int d = E[EE + t];
            atomicOr(&smask[wid][d >> 5], 1u << (d & 31));
        }
    }
    __syncwarp();
    unsigned m = (lane < 12) ? smask[wid][lane] : 0u;
    int cnt = __popc(m);
#pragma unroll
    for (int o = 16; o; o >>= 1) cnt += __shfl_xor_sync(0xffffffffu, cnt, o);
    if (lane == 0) g_deg[g][node] = (float)cnt;
}

// ---------------- lin0: 16 rows per block (latency fix) ---------------------
__global__ void k_lin0(const float* __restrict__ f1, const float* __restrict__ f2,
                       const float* __restrict__ w1, const float* __restrict__ b1,
                       const float* __restrict__ w2, const float* __restrict__ b2) {
    int g = blockIdx.y, rt = blockIdx.x;       // 24 row tiles of 16
    const float* F = g ? f2 : f1;
    __shared__ float xs[16][33];
    __shared__ float w1s[33 * 64];
    __shared__ float hid[16 * 64];
    int tid = threadIdx.x;
    for (int idx = tid; idx < 33 * 64; idx += 256) w1s[idx] = w1[idx];
    for (int idx = tid; idx < 16 * 32; idx += 256) xs[idx >> 5][idx & 31] = F[rt * 512 + idx];
    if (tid < 16) xs[tid][32] = g_deg[g][rt * 16 + tid];
    for (int idx = tid; idx < 16 * 64; idx += 256)
        g_agg[g][rt * 16 + (idx >> 6)][idx & 63] = 0.f;
    __syncthreads();
    int c = tid & 63, r0 = tid >> 6;
#pragma unroll 1
    for (int rr = 0; rr < 4; rr++) {
        int r = r0 + rr * 4;
        float acc = b1[c];
#pragma unroll
        for (int d = 0; d < 33; d++) acc += xs[r][d] * w1s[d * 64 + c];
        hid[r * 64 + c] = fmaxf(acc, 0.f);
    }
    __syncthreads();
#pragma unroll 1
    for (int rr = 0; rr < 4; rr++) {
        int r = r0 + rr * 4;
        float acc = b2[c];
#pragma unroll
        for (int m = 0; m < 64; m++) acc += hid[r * 64 + m] * w2[m * 64 + c];
        int row = rt * 16 + r;
        g_h[g][0][row][c] = acc;
        g_hcur[g][row][c] = acc;   // first GIN consumes h0 WITHOUT relu
    }
}

// ---------------- GIN aggregation ------------------------------------------
__global__ void k_agg(const int* __restrict__ e1, const int* __restrict__ e2) {
    int idx = blockIdx.x * 256 + threadIdx.x;          // 2*3456*64 threads
    int c = idx & 63;
    int e = (idx >> 6) % EE;
    int g = idx / (EE * 64);
    const int* E = g ? e2 : e1;
    atomicAdd(&g_agg[g][E[EE + e]][c], g_hcur[g][E[e]][c]);
}

// ---------------- GIN MLP: 16 rows per block (latency fix) ------------------
__global__ void k_mlp(const float* __restrict__ gw1, const float* __restrict__ gb1,
                      const float* __restrict__ gw2, const float* __restrict__ gb2,
                      const float* __restrict__ geps, int l) {
    int g = blockIdx.y, rt = blockIdx.x;       // 24 tiles of 16 rows
    __shared__ float zs[16][64];
    __shared__ float ws[64 * 64];
    __shared__ float hid[16 * 64];
    int tid = threadIdx.x;
    float eps1 = 1.f + geps[l];
    const float* w1 = gw1 + l * 4096;
    const float* w2 = gw2 + l * 4096;
    for (int idx = tid; idx < 4096; idx += 256) ws[idx] = w1[idx];
    for (int idx = tid; idx < 1024; idx += 256) {
        int r = idx >> 6, d = idx & 63, row = rt * 16 + r;
        zs[r][d] = eps1 * g_hcur[g][row][d] + g_agg[g][row][d];
    }
    __syncthreads();
    int c = tid & 63, r0 = tid >> 6;
#pragma unroll 1
    for (int rr = 0; rr < 4; rr++) {
        int r = r0 + rr * 4;
        float acc = gb1[l * 64 + c];
#pragma unroll
        for (int d = 0; d < 64; d++) acc += zs[r][d] * ws[d * 64 + c];
        hid[r * 64 + c] = fmaxf(acc, 0.f);
    }
    __syncthreads();
#pragma unroll 1
    for (int rr = 0; rr < 4; rr++) {
        int r = r0 + rr * 4;
        float acc = gb2[l * 64 + c];
#pragma unroll
        for (int m = 0; m < 64; m++) acc += hid[r * 64 + m] * w2[m * 64 + c];
        g_z[g][rt * 16 + r][c] = acc;
    }
}

// ---------------- BatchNorm + relu + zero agg -------------------------------
__global__ void k_bn(const float* __restrict__ gamma, const float* __restrict__ beta, int l) {
    int c = blockIdx.x, g = blockIdx.y, t = threadIdx.x;   // 384 threads
    __shared__ float red[12];
    __shared__ float bc;
    float val = g_z[g][t][c];
    float s = val;
#pragma unroll
    for (int o = 16; o; o >>= 1) s += __shfl_xor_sync(0xffffffffu, s, o);
    if ((t & 31) == 0) red[t >> 5] = s;
    __syncthreads();
    if (t < 32) {
        float v = (t < 12) ? red[t] : 0.f;
#pragma unroll
        for (int o = 16; o; o >>= 1) v += __shfl_xor_sync(0xffffffffu, v, o);
        if (t == 0) bc = v * (1.f / 384.f);
    }
    __syncthreads();
    float mu = bc;
    __syncthreads();
    float d = val - mu;
    float s2 = d * d;
#pragma unroll
    for (int o = 16; o; o >>= 1) s2 += __shfl_xor_sync(0xffffffffu, s2, o);
    if ((t & 31) == 0) red[t >> 5] = s2;
    __syncthreads();
    if (t < 32) {
        float v = (t < 12) ? red[t] : 0.f;
#pragma unroll
        for (int o = 16; o; o >>= 1) v += __shfl_xor_sync(0xffffffffu, v, o);
        if (t == 0) bc = v * (1.f / 384.f);
    }
    __syncthreads();
    float var = bc;
    float norm = d * rsqrtf(var + 1e-5f) * gamma[l * 64 + c] + beta[l * 64 + c];
    g_h[g][l + 1][t][c] = norm;
    g_hcur[g][t][c] = fmaxf(norm, 0.f);
    g_agg[g][t][c] = 0.f;
}

// ---------------- A^T[l,i,e,k] = sum_d h1[l,i,d]*ged[l,k,d,e] ---------------
__global__ void k_A(const float* __restrict__ ged) {
    int l = blockIdx.x, it = blockIdx.y * 16;
    __shared__ float h1s[16][64];
    int tid = threadIdx.x;
    for (int idx = tid; idx < 1024; idx += 256)
        h1s[idx >> 6][idx & 63] = g_h[0][l][it + (idx >> 6)][idx & 63];
    __syncthreads();
    int e = tid & 63, kq = tid >> 6;
#pragma unroll 1
    for (int kk2 = 0; kk2 < 8; kk2++) {
        int k = kq * 8 + kk2;
        float4 a0 = make_float4(0.f, 0.f, 0.f, 0.f);
        float4 a1 = make_float4(0.f, 0.f, 0.f, 0.f);
        float4 a2 = make_float4(0.f, 0.f, 0.f, 0.f);
        float4 a3 = make_float4(0.f, 0.f, 0.f, 0.f);
        const float* mp = ged + ((l * KK + k) * 64) * 64 + e;
#pragma unroll 4
        for (int d = 0; d < 64; d++) {
            float m = mp[d * 64];
            a0.x += h1s[0][d] * m;  a0.y += h1s[1][d] * m;
            a0.z += h1s[2][d] * m;  a0.w += h1s[3][d] * m;
            a1.x += h1s[4][d] * m;  a1.y += h1s[5][d] * m;
            a1.z += h1s[6][d] * m;  a1.w += h1s[7][d] * m;
            a2.x += h1s[8][d] * m;  a2.y += h1s[9][d] * m;
            a2.z += h1s[10][d] * m; a2.w += h1s[11][d] * m;
            a3.x += h1s[12][d] * m; a3.y += h1s[13][d] * m;
            a3.z += h1s[14][d] * m; a3.w += h1s[15][d] * m;
        }
        g_AT[l][it + 0][e][k]  = a0.x;  g_AT[l][it + 1][e][k]  = a0.y;
        g_AT[l][it + 2][e][k]  = a0.z;  g_AT[l][it + 3][e][k]  = a0.w;
        g_AT[l][it + 4][e][k]  = a1.x;  g_AT[l][it + 5][e][k]  = a1.y;
        g_AT[l][it + 6][e][k]  = a1.z;  g_AT[l][it + 7][e][k]  = a1.w;
        g_AT[l][it + 8][e][k]  = a2.x;  g_AT[l][it + 9][e][k]  = a2.y;
        g_AT[l][it + 10][e][k] = a2.z;  g_AT[l][it + 11][e][k] = a2.w;
        g_AT[l][it + 12][e][k] = a3.x;  g_AT[l][it + 13][e][k] = a3.y;
        g_AT[l][it + 14][e][k] = a3.z;  g_AT[l][it + 15][e][k] = a3.w;
    }
}

// ---------------- transpose h2 ----------------------------------------------
__global__ void k_h2T() {
    int idx = blockIdx.x * 256 + threadIdx.x;
    if (idx >= NLAY * 64 * NN) return;
    int l = idx / (64 * NN), rem = idx % (64 * NN);
    int e = rem / NN, j = rem % NN;
    g_h2T[l][e][j] = g_h[1][l][j][e];
}

// ---------------- float4 helpers (structs only; no arrays) ------------------
__device__ __forceinline__ float4 shfl4(float4 v, int s) {
    float4 r;
    r.x = __shfl_sync(0xffffffffu, v.x, s);
    r.y = __shfl_sync(0xffffffffu, v.y, s);
    r.z = __shfl_sync(0xffffffffu, v.z, s);
    r.w = __shfl_sync(0xffffffffu, v.w, s);
    return r;
}
__device__ __forceinline__ float sigm_f(float x) { return 1.f / (1.f + __expf(-x)); }
__device__ __forceinline__ float tanh_f(float x) { return 1.f - 2.f / (1.f + __expf(2.f * x)); }
__device__ __forceinline__ float4 set4(float v) { return make_float4(v, v, v, v); }

// ---------------- phase 1: GRU + layer attention -> g_pat, g_X --------------
// lane = channel k; warp = 4 pairs (j0..j0+3) held in float4 components.
__global__ void __launch_bounds__(256)
k_pat(const float* __restrict__ wih, const float* __restrict__ whh,
      const float* __restrict__ bih, const float* __restrict__ bhh,
      const float* __restrict__ wattn, const float* __restrict__ wattnb,
      const float* __restrict__ vattn) {
    __shared__ float s_AT[2048];       // [e*32+k] for current layer
    __shared__ float s_wih[3072];      // [m*96+c] (transposed)
    __shared__ float s_whh[3072];
    __shared__ float s_wa[1024];       // wattn [m*32+kp] direct

    int tid = threadIdx.x, i = blockIdx.x, jb = blockIdx.y;
    int w = tid >> 5, k = tid & 31;
    int j0 = jb * 32 + w * 4;

    for (int idx = tid; idx < 3072; idx += 256) {
        int m = idx / 96, c = idx - m * 96;
        s_wih[idx] = wih[c * 32 + m];
        s_whh[idx] = whh[c * 32 + m];
    }
    for (int idx = tid; idx < 1024; idx += 256) s_wa[idx] = wattn[idx];

    float bihr = bih[k], bihz = bih[32 + k], bihn = bih[64 + k];
    float bhhr = bhh[k], bhhz = bhh[32 + k], bhhn = bhh[64 + k];
    float wabk = wattnb[k], vk = vattn[k];

    float4 h4 = set4(0.f), pacc = set4(0.f);
    float4 M4 = set4(-1e30f), S4 = set4(0.f);

#pragma unroll 1
    for (int l = 0; l < 6; l++) {
        __syncthreads();
        const float* src = &g_AT[l][i][0][0];
        for (int idx = tid; idx < 2048; idx += 256) s_AT[idx] = src[idx];
        __syncthreads();

        // x_k = sum_e A[k][e] * h2[e][j]  (4 pairs)
        const float* h2b = &g_h2T[l][0][0];
        float4 h2lo = *(const float4*)(h2b + k * NN + j0);
        float4 h2hi = *(const float4*)(h2b + (32 + k) * NN + j0);
        float4 x4 = set4(0.f);
#pragma unroll 4
        for (int e = 0; e < 32; e++) {
            float4 v = shfl4(h2lo, e);
            float a = s_AT[e * 32 + k];
            x4.x += a * v.x; x4.y += a * v.y; x4.z += a * v.z; x4.w += a * v.w;
            float4 v2 = shfl4(h2hi, e);
            float a2 = s_AT[(32 + e) * 32 + k];
            x4.x += a2 * v2.x; x4.y += a2 * v2.y; x4.z += a2 * v2.z; x4.w += a2 * v2.w;
        }
        // persist x for phase 2 (k_ctx) — streaming store, no L2 allocate
        __stcg(&g_X[l][i][j0 + 0][k], x4.x);
        __stcg(&g_X[l][i][j0 + 1][k], x4.y);
        __stcg(&g_X[l][i][j0 + 2][k], x4.z);
        __stcg(&g_X[l][i][j0 + 3][k], x4.w);

        // GRU gates via shuffle-broadcast of x and h
        float4 air = set4(bihr), aiz = set4(bihz), ain = set4(bihn);
        float4 ahr = set4(bhhr), ahz = set4(bhhz), ahn = set4(bhhn);
#pragma unroll 4
        for (int m = 0; m < 32; m++) {
            float4 xm = shfl4(x4, m);
            float4 hm = shfl4(h4, m);
            float wir = s_wih[m * 96 + k], wiz = s_wih[m * 96 + 32 + k], win = s_wih[m * 96 + 64 + k];
            float whr = s_whh[m * 96 + k], whz = s_whh[m * 96 + 32 + k], whn = s_whh[m * 96 + 64 + k];
            air.x += wir * xm.x; air.y += wir * xm.y; air.z += wir * xm.z; air.w += wir * xm.w;
            aiz.x += wiz * xm.x; aiz.y += wiz * xm.y; aiz.z += wiz * xm.z; aiz.w += wiz * xm.w;
            ain.x += win * xm.x; ain.y += win * xm.y; ain.z += win * xm.z; ain.w += win * xm.w;
            ahr.x += whr * hm.x; ahr.y += whr * hm.y; ahr.z += whr * hm.z; ahr.w += whr * hm.w;
            ahz.x += whz * hm.x; ahz.y += whz * hm.y; ahz.z += whz * hm.z; ahz.w += whz * hm.w;
            ahn.x += whn * hm.x; ahn.y += whn * hm.y; ahn.z += whn * hm.z; ahn.w += whn * hm.w;
        }
        float rx = sigm_f(air.x + ahr.x), ry = sigm_f(air.y + ahr.y);
        float rz = sigm_f(air.z + ahr.z), rw = sigm_f(air.w + ahr.w);
        float zx = sigm_f(aiz.x + ahz.x), zy = sigm_f(aiz.y + ahz.y);
        float zz = sigm_f(aiz.z + ahz.z), zw = sigm_f(aiz.w + ahz.w);
        float nx = tanh_f(ain.x + rx * ahn.x), ny = tanh_f(ain.y + ry * ahn.y);
        float nz = tanh_f(ain.z + rz * ahn.z), nw = tanh_f(ain.w + rw * ahn.w);
        h4.x = (1.f - zx) * nx + zx * h4.x;
        h4.y = (1.f - zy) * ny + zy * h4.y;
        h4.z = (1.f - zz) * nz + zz * h4.z;
        h4.w = (1.f - zw) * nw + zw * h4.w;

        // attention score
        float4 t4 = set4(wabk);
#pragma unroll 4
        for (int m = 0; m < 32; m++) {
            float4 hm = shfl4(h4, m);
            float wv_ = s_wa[m * 32 + k];
            t4.x += wv_ * hm.x; t4.y += wv_ * hm.y; t4.z += wv_ * hm.z; t4.w += wv_ * hm.w;
        }
        t4.x = tanh_f(t4.x) * vk; t4.y = tanh_f(t4.y) * vk;
        t4.z = tanh_f(t4.z) * vk; t4.w = tanh_f(t4.w) * vk;
#pragma unroll
        for (int o = 16; o; o >>= 1) {
            t4.x += __shfl_xor_sync(0xffffffffu, t4.x, o);
            t4.y += __shfl_xor_sync(0xffffffffu, t4.y, o);
            t4.z += __shfl_xor_sync(0xffffffffu, t4.z, o);
            t4.w += __shfl_xor_sync(0xffffffffu, t4.w, o);
        }
        float4 nm4;
        nm4.x = fmaxf(M4.x, t4.x); nm4.y = fmaxf(M4.y, t4.y);
        nm4.z = fmaxf(M4.z, t4.z); nm4.w = fmaxf(M4.w, t4.w);
        float f0x = __expf(M4.x - nm4.x), f0y = __expf(M4.y - nm4.y);
        float f0z = __expf(M4.z - nm4.z), f0w = __expf(M4.w - nm4.w);
        float px = __expf(t4.x - nm4.x), py = __expf(t4.y - nm4.y);
        float pz = __expf(t4.z - nm4.z), pw = __expf(t4.w - nm4.w);
        S4.x = S4.x * f0x + px; S4.y = S4.y * f0y + py;
        S4.z = S4.z * f0z + pz; S4.w = S4.w * f0w + pw;
        pacc.x = pacc.x * f0x + px * h4.x;
        pacc.y = pacc.y * f0y + py * h4.y;
        pacc.z = pacc.z * f0z + pz * h4.z;
        pacc.w = pacc.w * f0w + pw * h4.w;
        M4 = nm4;
    }
    g_pat[i][j0 + 0][k] = pacc.x / S4.x;
    g_pat[i][j0 + 1][k] = pacc.y / S4.y;
    g_pat[i][j0 + 2][k] = pacc.z / S4.z;
    g_pat[i][j0 + 3][k] = pacc.w / S4.w;
}

// ---------------- phase 2: q/k/v + layer softmax -> context -----------------
// x loaded from g_X (no recompute).
__global__ void __launch_bounds__(256)
k_ctx(const float* __restrict__ wq1, const float* __restrict__ wq1b,
      const float* __restrict__ wq2, const float* __restrict__ wq2b,
      const float* __restrict__ wk, const float* __restrict__ wkb,
      const float* __restrict__ wv, const float* __restrict__ wvb,
      float* __restrict__ out) {
    __shared__ float s_wq1[1024];      // [m*32+kp] direct
    __shared__ float s_wq2[1024];
    __shared__ float s_wkT[1024];      // [p*32+e] (transposed)
    __shared__ float s_wv[1024];       // [p*32+k] direct

    int tid = threadIdx.x, i = blockIdx.x, jb = blockIdx.y;
    int w = tid >> 5, k = tid & 31;
    int j0 = jb * 32 + w * 4;

    for (int idx = tid; idx < 1024; idx += 256) {
        int p = idx >> 5, e = idx & 31;
        s_wq1[idx] = wq1[idx];
        s_wq2[idx] = wq2[idx];
        s_wv[idx]  = wv[idx];
        s_wkT[idx] = wk[e * 32 + p];
    }
    float wq1bk = wq1b[k], wq2bk = wq2b[k], wkbk = wkb[k], wvbk = wvb[k];
    __syncthreads();

    float4 pat;
    pat.x = g_pat[i][j0 + 0][k];
    pat.y = g_pat[i][j0 + 1][k];
    pat.z = g_pat[i][j0 + 2][k];
    pat.w = g_pat[i][j0 + 3][k];

    float4 t1 = set4(wq1bk);
#pragma unroll 4
    for (int m = 0; m < 32; m++) {
        float4 pm = shfl4(pat, m);
        float wv_ = s_wq1[m * 32 + k];
        t1.x += wv_ * pm.x; t1.y += wv_ * pm.y; t1.z += wv_ * pm.z; t1.w += wv_ * pm.w;
    }
    t1.x = fmaxf(t1.x, 0.f); t1.y = fmaxf(t1.y, 0.f);
    t1.z = fmaxf(t1.z, 0.f); t1.w = fmaxf(t1.w, 0.f);

    float4 q4 = set4(wq2bk);
#pragma unroll 4
    for (int m = 0; m < 32; m++) {
        float4 tm = shfl4(t1, m);
        float wv_ = s_wq2[m * 32 + k];
        q4.x += wv_ * tm.x; q4.y += wv_ * tm.y; q4.z += wv_ * tm.z; q4.w += wv_ * tm.w;
    }

    float4 qk4 = set4(0.f);        // qk_e = sum_p wk[e][p] q_p ; lane = e
#pragma unroll 4
    for (int p = 0; p < 32; p++) {
        float4 qm = shfl4(q4, p);
        float wv_ = s_wkT[p * 32 + k];
        qk4.x += wv_ * qm.x; qk4.y += wv_ * qm.y; qk4.z += wv_ * qm.z; qk4.w += wv_ * qm.w;
    }
    float4 qb4;
    qb4.x = q4.x * wkbk; qb4.y = q4.y * wkbk; qb4.z = q4.z * wkbk; qb4.w = q4.w * wkbk;
#pragma unroll
    for (int o = 16; o; o >>= 1) {
        qb4.x += __shfl_xor_sync(0xffffffffu, qb4.x, o);
        qb4.y += __shfl_xor_sync(0xffffffffu, qb4.y, o);
        qb4.z += __shfl_xor_sync(0xffffffffu, qb4.z, o);
        qb4.w += __shfl_xor_sync(0xffffffffu, qb4.w, o);
    }

    float4 sacc = set4(0.f), M4 = set4(-1e30f), S4 = set4(0.f);
#pragma unroll 1
    for (int l = 0; l < 6; l++) {
        float4 x4;
        x4.x = g_X[l][i][j0 + 0][k];
        x4.y = g_X[l][i][j0 + 1][k];
        x4.z = g_X[l][i][j0 + 2][k];
        x4.w = g_X[l][i][j0 + 3][k];

        float4 s4;
        s4.x = qk4.x * x4.x; s4.y = qk4.y * x4.y; s4.z = qk4.z * x4.z; s4.w = qk4.w * x4.w;
#pragma unroll
        for (int o = 16; o; o >>= 1) {
            s4.x += __shfl_xor_sync(0xffffffffu, s4.x, o);
            s4.y += __shfl_xor_sync(0xffffffffu, s4.y, o);
            s4.z += __shfl_xor_sync(0xffffffffu, s4.z, o);
            s4.w += __shfl_xor_sync(0xffffffffu, s4.w, o);
        }
        s4.x = (s4.x + qb4.x) * 0.17677669529663687f;
        s4.y = (s4.y + qb4.y) * 0.17677669529663687f;
        s4.z = (s4.z + qb4.z) * 0.17677669529663687f;
        s4.w = (s4.w + qb4.w) * 0.17677669529663687f;

        float4 nm4;
        nm4.x = fmaxf(M4.x, s4.x); nm4.y = fmaxf(M4.y, s4.y);
        nm4.z = fmaxf(M4.z, s4.z); nm4.w = fmaxf(M4.w, s4.w);
        float f0x = __expf(M4.x - nm4.x), f0y = __expf(M4.y - nm4.y);
        float f0z = __expf(M4.z - nm4.z), f0w = __expf(M4.w - nm4.w);
        float px = __expf(s4.x - nm4.x), py = __expf(s4.y - nm4.y);
        float pz = __expf(s4.z - nm4.z), pw = __expf(s4.w - nm4.w);
        S4.x = S4.x * f0x + px; S4.y = S4.y * f0y + py;
        S4.z = S4.z * f0z + pz; S4.w = S4.w * f0w + pw;
        sacc.x = sacc.x * f0x + px * x4.x;
        sacc.y = sacc.y * f0y + py * x4.y;
        sacc.z = sacc.z * f0z + pz * x4.z;
        sacc.w = sacc.w * f0w + pw * x4.w;
        M4 = nm4;
    }
    sacc.x /= S4.x; sacc.y /= S4.y; sacc.z /= S4.z; sacc.w /= S4.w;

    float4 c4 = set4(wvbk);
#pragma unroll 4
    for (int p = 0; p < 32; p++) {
        float4 sm4 = shfl4(sacc, p);
        float wv_ = s_wv[p * 32 + k];
        c4.x += wv_ * sm4.x; c4.y += wv_ * sm4.y; c4.z += wv_ * sm4.z; c4.w += wv_ * sm4.w;
    }
    out[((size_t)i * NN + j0 + 0) * KK + k] = c4.x;
    out[((size_t)i * NN + j0 + 1) * KK + k] = c4.y;
    out[((size_t)i * NN + j0 + 2) * KK + k] = c4.z;
    out[((size_t)i * NN + j0 + 3) * KK + k] = c4.w;
}

// ---------------- host ------------------------------------------------------
extern "C" void kernel_launch(void* const* d_in, const int* in_sizes, int n_in,
                              void* d_out, int out_size) {
    const float* f1   = (const float*)d_in[0];
    const float* f2   = (const float*)d_in[1];
    const float* l0w1 = (const float*)d_in[2];
    const float* l0b1 = (const float*)d_in[3];
    const float* l0w2 = (const float*)d_in[4];
    const float* l0b2 = (const float*)d_in[5];
    const float* geps = (const float*)d_in[6];
    const float* gw1  = (const float*)d_in[7];
    const float* gb1  = (const float*)d_in[8];
    const float* gw2  = (const float*)d_in[9];
    const float* gb2  = (const float*)d_in[10];
    const float* gga  = (const float*)d_in[11];
    const float* gbe  = (const float*)d_in[12];
    const float* ged  = (const float*)d_in[13];
    const float* wih  = (const float*)d_in[14];
    const float* whh  = (const float*)d_in[15];
    const float* bih  = (const float*)d_in[16];
    const float* bhh  = (const float*)d_in[17];
    const float* waw  = (const float*)d_in[18];
    const float* wab  = (const float*)d_in[19];
    const float* vat  = (const float*)d_in[20];
    const float* wq1  = (const float*)d_in[21];
    const float* wq1b = (const float*)d_in[22];
    const float* wq2  = (const float*)d_in[23];
    const float* wq2b = (const float*)d_in[24];
    const float* wk   = (const float*)d_in[25];
    const float* wkb  = (const float*)d_in[26];
    const float* wv   = (const float*)d_in[27];
    const float* wvb  = (const float*)d_in[28];
    const int*   e1   = (const int*)d_in[29];
    const int*   e2   = (const int*)d_in[30];
    float* out = (float*)d_out;

    k_deg<<<dim3(96, 2), 128>>>(e1, e2);
    k_lin0<<<dim3(24, 2), 256>>>(f1, f2, l0w1, l0b1, l0w2, l0b2);
    for (int l = 0; l < 5; l++) {
        k_agg<<<1728, 256>>>(e1, e2);
        k_mlp<<<dim3(24, 2), 256>>>(gw1, gb1, gw2, gb2, geps, l);
        k_bn<<<dim3(64, 2), 384>>>(gga, gbe, l);
    }
    k_A<<<dim3(6, 24), 256>>>(ged);
    k_h2T<<<576, 256>>>();
    k_pat<<<dim3(384, 12), 256>>>(wih, whh, bih, bhh, waw, wab, vat);
    k_ctx<<<dim3(384, 12), 256>>>(wq1, wq1b, wq2, wq2b, wk, wkb, wv, wvb, out);
}

// round 10
// speedup vs baseline: 1.5517x; 1.2512x over previous
#include <cuda_runtime.h>
#include <cuda_bf16.h>
#include <math.h>

#define NN   384
#define EE   3456
#define ENS  3072
#define F3   64
#define KK   32
#define NLAY 6

__device__ float g_h[2][NLAY][NN][F3];
__device__ float g_hcur[2][NN][F3];
__device__ float g_agg[2][NN][F3];
__device__ float g_z[2][NN][F3];
__device__ float g_deg[2][NN];
__device__ float g_AT[NLAY][NN][F3][KK];   // A transposed: [l][i][e][k]
__device__ float g_h2T[NLAY][F3][NN];
__device__ float g_pat[NN][NN][KK];
__device__ float g_X[NLAY][NN][NN][KK];    // stack values, written by k_pat

// ---------------- degrees: distinct dst per src over first 3072 edges -------
__global__ void k_deg(const int* __restrict__ e1, const int* __restrict__ e2) {
    __shared__ unsigned smask[4][12];
    int g = blockIdx.y;
    const int* E = g ? e2 : e1;
    int wid = threadIdx.x >> 5, lane = threadIdx.x & 31;
    int node = blockIdx.x * 4 + wid;
    if (lane < 12) smask[wid][lane] = 0u;
    __syncwarp();
    for (int t = lane; t < ENS; t += 32) {
        if (E[t] == node) {
            int d = E[EE + t];
            atomicOr(&smask[wid][d >> 5], 1u << (d & 31));
        }
    }
    __syncwarp();
    unsigned m = (lane < 12) ? smask[wid][lane] : 0u;
    int cnt = __popc(m);
#pragma unroll
    for (int o = 16; o; o >>= 1) cnt += __shfl_xor_sync(0xffffffffu, cnt, o);
    if (lane == 0) g_deg[g][node] = (float)cnt;
}

// ---------------- lin0: 16 rows per block -----------------------------------
__global__ void k_lin0(const float* __restrict__ f1, const float* __restrict__ f2,
                       const float* __restrict__ w1, const float* __restrict__ b1,
                       const float* __restrict__ w2, const float* __restrict__ b2) {
    int g = blockIdx.y, rt = blockIdx.x;       // 24 row tiles of 16
    const float* F = g ? f2 : f1;
    __shared__ float xs[16][33];
    __shared__ float w1s[33 * 64];
    __shared__ float hid[16 * 64];
    int tid = threadIdx.x;
    for (int idx = tid; idx < 33 * 64; idx += 256) w1s[idx] = w1[idx];
    for (int idx = tid; idx < 16 * 32; idx += 256) xs[idx >> 5][idx & 31] = F[rt * 512 + idx];
    if (tid < 16) xs[tid][32] = g_deg[g][rt * 16 + tid];
    for (int idx = tid; idx < 16 * 64; idx += 256)
        g_agg[g][rt * 16 + (idx >> 6)][idx & 63] = 0.f;
    __syncthreads();
    int c = tid & 63, r0 = tid >> 6;
#pragma unroll 1
    for (int rr = 0; rr < 4; rr++) {
        int r = r0 + rr * 4;
        float acc = b1[c];
#pragma unroll
        for (int d = 0; d < 33; d++) acc += xs[r][d] * w1s[d * 64 + c];
        hid[r * 64 + c] = fmaxf(acc, 0.f);
    }
    __syncthreads();
#pragma unroll 1
    for (int rr = 0; rr < 4; rr++) {
        int r = r0 + rr * 4;
        float acc = b2[c];
#pragma unroll
        for (int m = 0; m < 64; m++) acc += hid[r * 64 + m] * w2[m * 64 + c];
        int row = rt * 16 + r;
        g_h[g][0][row][c] = acc;
        g_hcur[g][row][c] = acc;   // first GIN consumes h0 WITHOUT relu
    }
}

// ---------------- GIN aggregation ------------------------------------------
__global__ void k_agg(const int* __restrict__ e1, const int* __restrict__ e2) {
    int idx = blockIdx.x * 256 + threadIdx.x;          // 2*3456*64 threads
    int c = idx & 63;
    int e = (idx >> 6) % EE;
    int g = idx / (EE * 64);
    const int* E = g ? e2 : e1;
    atomicAdd(&g_agg[g][E[EE + e]][c], g_hcur[g][E[e]][c]);
}

// ---------------- GIN MLP: 16 rows per block --------------------------------
__global__ void k_mlp(const float* __restrict__ gw1, const float* __restrict__ gb1,
                      const float* __restrict__ gw2, const float* __restrict__ gb2,
                      const float* __restrict__ geps, int l) {
    int g = blockIdx.y, rt = blockIdx.x;       // 24 tiles of 16 rows
    __shared__ float zs[16][64];
    __shared__ float ws[64 * 64];
    __shared__ float hid[16 * 64];
    int tid = threadIdx.x;
    float eps1 = 1.f + geps[l];
    const float* w1 = gw1 + l * 4096;
    const float* w2 = gw2 + l * 4096;
    for (int idx = tid; idx < 4096; idx += 256) ws[idx] = w1[idx];
    for (int idx = tid; idx < 1024; idx += 256) {
        int r = idx >> 6, d = idx & 63, row = rt * 16 + r;
        zs[r][d] = eps1 * g_hcur[g][row][d] + g_agg[g][row][d];
    }
    __syncthreads();
    int c = tid & 63, r0 = tid >> 6;
#pragma unroll 1
    for (int rr = 0; rr < 4; rr++) {
        int r = r0 + rr * 4;
        float acc = gb1[l * 64 + c];
#pragma unroll
        for (int d = 0; d < 64; d++) acc += zs[r][d] * ws[d * 64 + c];
        hid[r * 64 + c] = fmaxf(acc, 0.f);
    }
    __syncthreads();
#pragma unroll 1
    for (int rr = 0; rr < 4; rr++) {
        int r = r0 + rr * 4;
        float acc = gb2[l * 64 + c];
#pragma unroll
        for (int m = 0; m < 64; m++) acc += hid[r * 64 + m] * w2[m * 64 + c];
        g_z[g][rt * 16 + r][c] = acc;
    }
}

// ---------------- BatchNorm + relu + zero agg -------------------------------
__global__ void k_bn(const float* __restrict__ gamma, const float* __restrict__ beta, int l) {
    int c = blockIdx.x, g = blockIdx.y, t = threadIdx.x;   // 384 threads
    __shared__ float red[12];
    __shared__ float bc;
    float val = g_z[g][t][c];
    float s = val;
#pragma unroll
    for (int o = 16; o; o >>= 1) s += __shfl_xor_sync(0xffffffffu, s, o);
    if ((t & 31) == 0) red[t >> 5] = s;
    __syncthreads();
    if (t < 32) {
        float v = (t < 12) ? red[t] : 0.f;
#pragma unroll
        for (int o = 16; o; o >>= 1) v += __shfl_xor_sync(0xffffffffu, v, o);
        if (t == 0) bc = v * (1.f / 384.f);
    }
    __syncthreads();
    float mu = bc;
    __syncthreads();
    float d = val - mu;
    float s2 = d * d;
#pragma unroll
    for (int o = 16; o; o >>= 1) s2 += __shfl_xor_sync(0xffffffffu, s2, o);
    if ((t & 31) == 0) red[t >> 5] = s2;
    __syncthreads();
    if (t < 32) {
        float v = (t < 12) ? red[t] : 0.f;
#pragma unroll
        for (int o = 16; o; o >>= 1) v += __shfl_xor_sync(0xffffffffu, v, o);
        if (t == 0) bc = v * (1.f / 384.f);
    }
    __syncthreads();
    float var = bc;
    float norm = d * rsqrtf(var + 1e-5f) * gamma[l * 64 + c] + beta[l * 64 + c];
    g_h[g][l + 1][t][c] = norm;
    g_hcur[g][t][c] = fmaxf(norm, 0.f);
    g_agg[g][t][c] = 0.f;
}

// ---------------- A^T[l,i,e,k] = sum_d h1[l,i,d]*ged[l,k,d,e] ---------------
__global__ void k_A(const float* __restrict__ ged) {
    int l = blockIdx.x, it = blockIdx.y * 16;
    __shared__ float h1s[16][64];
    int tid = threadIdx.x;
    for (int idx = tid; idx < 1024; idx += 256)
        h1s[idx >> 6][idx & 63] = g_h[0][l][it + (idx >> 6)][idx & 63];
    __syncthreads();
    int e = tid & 63, kq = tid >> 6;
#pragma unroll 1
    for (int kk2 = 0; kk2 < 8; kk2++) {
        int k = kq * 8 + kk2;
        float4 a0 = make_float4(0.f, 0.f, 0.f, 0.f);
        float4 a1 = make_float4(0.f, 0.f, 0.f, 0.f);
        float4 a2 = make_float4(0.f, 0.f, 0.f, 0.f);
        float4 a3 = make_float4(0.f, 0.f, 0.f, 0.f);
        const float* mp = ged + ((l * KK + k) * 64) * 64 + e;
#pragma unroll 4
        for (int d = 0; d < 64; d++) {
            float m = mp[d * 64];
            a0.x += h1s[0][d] * m;  a0.y += h1s[1][d] * m;
            a0.z += h1s[2][d] * m;  a0.w += h1s[3][d] * m;
            a1.x += h1s[4][d] * m;  a1.y += h1s[5][d] * m;
            a1.z += h1s[6][d] * m;  a1.w += h1s[7][d] * m;
            a2.x += h1s[8][d] * m;  a2.y += h1s[9][d] * m;
            a2.z += h1s[10][d] * m; a2.w += h1s[11][d] * m;
            a3.x += h1s[12][d] * m; a3.y += h1s[13][d] * m;
            a3.z += h1s[14][d] * m; a3.w += h1s[15][d] * m;
        }
        g_AT[l][it + 0][e][k]  = a0.x;  g_AT[l][it + 1][e][k]  = a0.y;
        g_AT[l][it + 2][e][k]  = a0.z;  g_AT[l][it + 3][e][k]  = a0.w;
        g_AT[l][it + 4][e][k]  = a1.x;  g_AT[l][it + 5][e][k]  = a1.y;
        g_AT[l][it + 6][e][k]  = a1.z;  g_AT[l][it + 7][e][k]  = a1.w;
        g_AT[l][it + 8][e][k]  = a2.x;  g_AT[l][it + 9][e][k]  = a2.y;
        g_AT[l][it + 10][e][k] = a2.z;  g_AT[l][it + 11][e][k] = a2.w;
        g_AT[l][it + 12][e][k] = a3.x;  g_AT[l][it + 13][e][k] = a3.y;
        g_AT[l][it + 14][e][k] = a3.z;  g_AT[l][it + 15][e][k] = a3.w;
    }
}

// ---------------- transpose h2 ----------------------------------------------
__global__ void k_h2T() {
    int idx = blockIdx.x * 256 + threadIdx.x;
    if (idx >= NLAY * 64 * NN) return;
    int l = idx / (64 * NN), rem = idx % (64 * NN);
    int e = rem / NN, j = rem % NN;
    g_h2T[l][e][j] = g_h[1][l][j][e];
}

// ---------------- helpers ---------------------------------------------------
__device__ __forceinline__ float4 shfl4(float4 v, int s) {
    float4 r;
    r.x = __shfl_sync(0xffffffffu, v.x, s);
    r.y = __shfl_sync(0xffffffffu, v.y, s);
    r.z = __shfl_sync(0xffffffffu, v.z, s);
    r.w = __shfl_sync(0xffffffffu, v.w, s);
    return r;
}
__device__ __forceinline__ float sigm_f(float x) { return 1.f / (1.f + __expf(-x)); }
__device__ __forceinline__ float tanh_f(float x) { return 1.f - 2.f / (1.f + __expf(2.f * x)); }
__device__ __forceinline__ float4 set4(float v) { return make_float4(v, v, v, v); }

// ---------------- phase 1: GRU + layer attention -> g_pat, g_X --------------
// lane = channel k; warp = 4 pairs. All cross-lane broadcasts via SMEM
// float4 (1 LDS.128 replaces 4 SHFLs) — kernel becomes FFMA-bound.
// Dynamic SMEM layout (floats):
//   s_wih 0      (3072)  [m*96+c] transposed
//   s_whh 3072   (3072)
//   s_wa  6144   (1024)  [m*32+kp]
//   s_AT  7168   (2048)  [e*32+k] current layer
//   s_h2  9216   (2048)  [e*32+jl] current layer, block's 32 j
//   s_x   11264  (1024)  [w][m][4 pairs]
//   s_h   12288  (1024)  [w][m][4 pairs]
#define KP_SMEM 13312
__global__ void __launch_bounds__(256)
k_pat(const float* __restrict__ wih, const float* __restrict__ whh,
      const float* __restrict__ bih, const float* __restrict__ bhh,
      const float* __restrict__ wattn, const float* __restrict__ wattnb,
      const float* __restrict__ vattn) {
    extern __shared__ float sm[];
    float* s_wih = sm;
    float* s_whh = sm + 3072;
    float* s_wa  = sm + 6144;
    float* s_AT  = sm + 7168;
    float* s_h2  = sm + 9216;
    float* s_x   = sm + 11264;
    float* s_h   = sm + 12288;

    int tid = threadIdx.x, i = blockIdx.x, jb = blockIdx.y;
    int w = tid >> 5, k = tid & 31;
    int j0 = jb * 32 + w * 4;

    for (int idx = tid; idx < 3072; idx += 256) {
        int m = idx / 96, c = idx - m * 96;
        s_wih[idx] = wih[c * 32 + m];
        s_whh[idx] = whh[c * 32 + m];
    }
    for (int idx = tid; idx < 1024; idx += 256) s_wa[idx] = wattn[idx];
    // init s_h to zeros (GRU h0 = 0)
    *(float4*)&s_h[(w * 32 + k) * 4] = set4(0.f);

    float bihr = bih[k], bihz = bih[32 + k], bihn = bih[64 + k];
    float bhhr = bhh[k], bhhz = bhh[32 + k], bhhn = bhh[64 + k];
    float wabk = wattnb[k], vk = vattn[k];

    float4 h4 = set4(0.f), pacc = set4(0.f);
    float4 M4 = set4(-1e30f), S4 = set4(0.f);

#pragma unroll 1
    for (int l = 0; l < 6; l++) {
        __syncthreads();
        {
            const float* srcA = &g_AT[l][i][0][0];
            for (int idx = tid; idx < 2048; idx += 256) s_AT[idx] = srcA[idx];
            const float* srcH = &g_h2T[l][0][jb * 32];
            for (int idx = tid; idx < 2048; idx += 256)
                s_h2[idx] = srcH[(idx >> 5) * NN + (idx & 31)];
        }
        __syncthreads();

        // x_k = sum_e A[e][k] * h2[e][j]   (4 pairs via float4 broadcast)
        float4 x4 = set4(0.f);
#pragma unroll 4
        for (int e = 0; e < 64; e++) {
            float a = s_AT[e * 32 + k];
            float4 hv = *(const float4*)&s_h2[e * 32 + w * 4];
            x4.x += a * hv.x; x4.y += a * hv.y; x4.z += a * hv.z; x4.w += a * hv.w;
        }
        // persist x for phase 2 — streaming store, no L2 allocate
        __stcg(&g_X[l][i][j0 + 0][k], x4.x);
        __stcg(&g_X[l][i][j0 + 1][k], x4.y);
        __stcg(&g_X[l][i][j0 + 2][k], x4.z);
        __stcg(&g_X[l][i][j0 + 3][k], x4.w);

        // share x across lanes via SMEM
        __syncwarp();
        *(float4*)&s_x[(w * 32 + k) * 4] = x4;
        __syncwarp();

        // GRU gates: broadcast xm/hm from SMEM (2 LDS.128 per m)
        float4 air = set4(bihr), aiz = set4(bihz), ain = set4(bihn);
        float4 ahr = set4(bhhr), ahz = set4(bhhz), ahn = set4(bhhn);
#pragma unroll 4
        for (int m = 0; m < 32; m++) {
            float4 xm = *(const float4*)&s_x[(w * 32 + m) * 4];
            float4 hm = *(const float4*)&s_h[(w * 32 + m) * 4];
            float wir = s_wih[m * 96 + k], wiz = s_wih[m * 96 + 32 + k], win = s_wih[m * 96 + 64 + k];
            float whr = s_whh[m * 96 + k], whz = s_whh[m * 96 + 32 + k], whn = s_whh[m * 96 + 64 + k];
            air.x += wir * xm.x; air.y += wir * xm.y; air.z += wir * xm.z; air.w += wir * xm.w;
            aiz.x += wiz * xm.x; aiz.y += wiz * xm.y; aiz.z += wiz * xm.z; aiz.w += wiz * xm.w;
            ain.x += win * xm.x; ain.y += win * xm.y; ain.z += win * xm.z; ain.w += win * xm.w;
            ahr.x += whr * hm.x; ahr.y += whr * hm.y; ahr.z += whr * hm.z; ahr.w += whr * hm.w;
            ahz.x += whz * hm.x; ahz.y += whz * hm.y; ahz.z += whz * hm.z; ahz.w += whz * hm.w;
            ahn.x += whn * hm.x; ahn.y += whn * hm.y; ahn.z += whn * hm.z; ahn.w += whn * hm.w;
        }
        float rx = sigm_f(air.x + ahr.x), ry = sigm_f(air.y + ahr.y);
        float rz = sigm_f(air.z + ahr.z), rw = sigm_f(air.w + ahr.w);
        float zx = sigm_f(aiz.x + ahz.x), zy = sigm_f(aiz.y + ahz.y);
        float zz = sigm_f(aiz.z + ahz.z), zw = sigm_f(aiz.w + ahz.w);
        float nx = tanh_f(ain.x + rx * ahn.x), ny = tanh_f(ain.y + ry * ahn.y);
        float nz = tanh_f(ain.z + rz * ahn.z), nw = tanh_f(ain.w + rw * ahn.w);
        h4.x = (1.f - zx) * nx + zx * h4.x;
        h4.y = (1.f - zy) * ny + zy * h4.y;
        h4.z = (1.f - zz) * nz + zz * h4.z;
        h4.w = (1.f - zw) * nw + zw * h4.w;

        // publish new h
        __syncwarp();
        *(float4*)&s_h[(w * 32 + k) * 4] = h4;
        __syncwarp();

        // attention score (hm broadcast from SMEM)
        float4 t4 = set4(wabk);
#pragma unroll 4
        for (int m = 0; m < 32; m++) {
            float4 hm = *(const float4*)&s_h[(w * 32 + m) * 4];
            float wv_ = s_wa[m * 32 + k];
            t4.x += wv_ * hm.x; t4.y += wv_ * hm.y; t4.z += wv_ * hm.z; t4.w += wv_ * hm.w;
        }
        t4.x = tanh_f(t4.x) * vk; t4.y = tanh_f(t4.y) * vk;
        t4.z = tanh_f(t4.z) * vk; t4.w = tanh_f(t4.w) * vk;
#pragma unroll
        for (int o = 16; o; o >>= 1) {
            t4.x += __shfl_xor_sync(0xffffffffu, t4.x, o);
            t4.y += __shfl_xor_sync(0xffffffffu, t4.y, o);
            t4.z += __shfl_xor_sync(0xffffffffu, t4.z, o);
            t4.w += __shfl_xor_sync(0xffffffffu, t4.w, o);
        }
        float4 nm4;
        nm4.x = fmaxf(M4.x, t4.x); nm4.y = fmaxf(M4.y, t4.y);
        nm4.z = fmaxf(M4.z, t4.z); nm4.w = fmaxf(M4.w, t4.w);
        float f0x = __expf(M4.x - nm4.x), f0y = __expf(M4.y - nm4.y);
        float f0z = __expf(M4.z - nm4.z), f0w = __expf(M4.w - nm4.w);
        float px = __expf(t4.x - nm4.x), py = __expf(t4.y - nm4.y);
        float pz = __expf(t4.z - nm4.z), pw = __expf(t4.w - nm4.w);
        S4.x = S4.x * f0x + px; S4.y = S4.y * f0y + py;
        S4.z = S4.z * f0z + pz; S4.w = S4.w * f0w + pw;
        pacc.x = pacc.x * f0x + px * h4.x;
        pacc.y = pacc.y * f0y + py * h4.y;
        pacc.z = pacc.z * f0z + pz * h4.z;
        pacc.w = pacc.w * f0w + pw * h4.w;
        M4 = nm4;
    }
    g_pat[i][j0 + 0][k] = pacc.x / S4.x;
    g_pat[i][j0 + 1][k] = pacc.y / S4.y;
    g_pat[i][j0 + 2][k] = pacc.z / S4.z;
    g_pat[i][j0 + 3][k] = pacc.w / S4.w;
}

// ---------------- phase 2: q/k/v + layer softmax -> context -----------------
__global__ void __launch_bounds__(256)
k_ctx(const float* __restrict__ wq1, const float* __restrict__ wq1b,
      const float* __restrict__ wq2, const float* __restrict__ wq2b,
      const float* __restrict__ wk, const float* __restrict__ wkb,
      const float* __restrict__ wv, const float* __restrict__ wvb,
      float* __restrict__ out) {
    __shared__ float s_wq1[1024];      // [m*32+kp] direct
    __shared__ float s_wq2[1024];
    __shared__ float s_wkT[1024];      // [p*32+e] (transposed)
    __shared__ float s_wv[1024];       // [p*32+k] direct

    int tid = threadIdx.x, i = blockIdx.x, jb = blockIdx.y;
    int w = tid >> 5, k = tid & 31;
    int j0 = jb * 32 + w * 4;

    for (int idx = tid; idx < 1024; idx += 256) {
        int p = idx >> 5, e = idx & 31;
        s_wq1[idx] = wq1[idx];
        s_wq2[idx] = wq2[idx];
        s_wv[idx]  = wv[idx];
        s_wkT[idx] = wk[e * 32 + p];
    }
    float wq1bk = wq1b[k], wq2bk = wq2b[k], wkbk = wkb[k], wvbk = wvb[k];
    __syncthreads();

    float4 pat;
    pat.x = g_pat[i][j0 + 0][k];
    pat.y = g_pat[i][j0 + 1][k];
    pat.z = g_pat[i][j0 + 2][k];
    pat.w = g_pat[i][j0 + 3][k];

    float4 t1 = set4(wq1bk);
#pragma unroll 4
    for (int m = 0; m < 32; m++) {
        float4 pm = shfl4(pat, m);
        float wv_ = s_wq1[m * 32 + k];
        t1.x += wv_ * pm.x; t1.y += wv_ * pm.y; t1.z += wv_ * pm.z; t1.w += wv_ * pm.w;
    }
    t1.x = fmaxf(t1.x, 0.f); t1.y = fmaxf(t1.y, 0.f);
    t1.z = fmaxf(t1.z, 0.f); t1.w = fmaxf(t1.w, 0.f);

    float4 q4 = set4(wq2bk);
#pragma unroll 4
    for (int m = 0; m < 32; m++) {
        float4 tm = shfl4(t1, m);
        float wv_ = s_wq2[m * 32 + k];
        q4.x += wv_ * tm.x; q4.y += wv_ * tm.y; q4.z += wv_ * tm.z; q4.w += wv_ * tm.w;
    }

    float4 qk4 = set4(0.f);        // qk_e = sum_p wk[e][p] q_p ; lane = e
#pragma unroll 4
    for (int p = 0; p < 32; p++) {
        float4 qm = shfl4(q4, p);
        float wv_ = s_wkT[p * 32 + k];
        qk4.x += wv_ * qm.x; qk4.y += wv_ * qm.y; qk4.z += wv_ * qm.z; qk4.w += wv_ * qm.w;
    }
    float4 qb4;
    qb4.x = q4.x * wkbk; qb4.y = q4.y * wkbk; qb4.z = q4.z * wkbk; qb4.w = q4.w * wkbk;
#pragma unroll
    for (int o = 16; o; o >>= 1) {
        qb4.x += __shfl_xor_sync(0xffffffffu, qb4.x, o);
        qb4.y += __shfl_xor_sync(0xffffffffu, qb4.y, o);
        qb4.z += __shfl_xor_sync(0xffffffffu, qb4.z, o);
        qb4.w += __shfl_xor_sync(0xffffffffu, qb4.w, o);
    }

    float4 sacc = set4(0.f), M4 = set4(-1e30f), S4 = set4(0.f);
#pragma unroll 1
    for (int l = 0; l < 6; l++) {
        float4 x4;
        x4.x = g_X[l][i][j0 + 0][k];
        x4.y = g_X[l][i][j0 + 1][k];
        x4.z = g_X[l][i][j0 + 2][k];
        x4.w = g_X[l][i][j0 + 3][k];

        float4 s4;
        s4.x = qk4.x * x4.x; s4.y = qk4.y * x4.y; s4.z = qk4.z * x4.z; s4.w = qk4.w * x4.w;
#pragma unroll
        for (int o = 16; o; o >>= 1) {
            s4.x += __shfl_xor_sync(0xffffffffu, s4.x, o);
            s4.y += __shfl_xor_sync(0xffffffffu, s4.y, o);
            s4.z += __shfl_xor_sync(0xffffffffu, s4.z, o);
            s4.w += __shfl_xor_sync(0xffffffffu, s4.w, o);
        }
        s4.x = (s4.x + qb4.x) * 0.17677669529663687f;
        s4.y = (s4.y + qb4.y) * 0.17677669529663687f;
        s4.z = (s4.z + qb4.z) * 0.17677669529663687f;
        s4.w = (s4.w + qb4.w) * 0.17677669529663687f;

        float4 nm4;
        nm4.x = fmaxf(M4.x, s4.x); nm4.y = fmaxf(M4.y, s4.y);
        nm4.z = fmaxf(M4.z, s4.z); nm4.w = fmaxf(M4.w, s4.w);
        float f0x = __expf(M4.x - nm4.x), f0y = __expf(M4.y - nm4.y);
        float f0z = __expf(M4.z - nm4.z), f0w = __expf(M4.w - nm4.w);
        float px = __expf(s4.x - nm4.x), py = __expf(s4.y - nm4.y);
        float pz = __expf(s4.z - nm4.z), pw = __expf(s4.w - nm4.w);
        S4.x = S4.x * f0x + px; S4.y = S4.y * f0y + py;
        S4.z = S4.z * f0z + pz; S4.w = S4.w * f0w + pw;
        sacc.x = sacc.x * f0x + px * x4.x;
        sacc.y = sacc.y * f0y + py * x4.y;
        sacc.z = sacc.z * f0z + pz * x4.z;
        sacc.w = sacc.w * f0w + pw * x4.w;
        M4 = nm4;
    }
    sacc.x /= S4.x; sacc.y /= S4.y; sacc.z /= S4.z; sacc.w /= S4.w;

    float4 c4 = set4(wvbk);
#pragma unroll 4
    for (int p = 0; p < 32; p++) {
        float4 sm4 = shfl4(sacc, p);
        float wv_ = s_wv[p * 32 + k];
        c4.x += wv_ * sm4.x; c4.y += wv_ * sm4.y; c4.z += wv_ * sm4.z; c4.w += wv_ * sm4.w;
    }
    out[((size_t)i * NN + j0 + 0) * KK + k] = c4.x;
    out[((size_t)i * NN + j0 + 1) * KK + k] = c4.y;
    out[((size_t)i * NN + j0 + 2) * KK + k] = c4.z;
    out[((size_t)i * NN + j0 + 3) * KK + k] = c4.w;
}

// ---------------- host ------------------------------------------------------
extern "C" void kernel_launch(void* const* d_in, const int* in_sizes, int n_in,
                              void* d_out, int out_size) {
    const float* f1   = (const float*)d_in[0];
    const float* f2   = (const float*)d_in[1];
    const float* l0w1 = (const float*)d_in[2];
    const float* l0b1 = (const float*)d_in[3];
    const float* l0w2 = (const float*)d_in[4];
    const float* l0b2 = (const float*)d_in[5];
    const float* geps = (const float*)d_in[6];
    const float* gw1  = (const float*)d_in[7];
    const float* gb1  = (const float*)d_in[8];
    const float* gw2  = (const float*)d_in[9];
    const float* gb2  = (const float*)d_in[10];
    const float* gga  = (const float*)d_in[11];
    const float* gbe  = (const float*)d_in[12];
    const float* ged  = (const float*)d_in[13];
    const float* wih  = (const float*)d_in[14];
    const float* whh  = (const float*)d_in[15];
    const float* bih  = (const float*)d_in[16];
    const float* bhh  = (const float*)d_in[17];
    const float* waw  = (const float*)d_in[18];
    const float* wab  = (const float*)d_in[19];
    const float* vat  = (const float*)d_in[20];
    const float* wq1  = (const float*)d_in[21];
    const float* wq1b = (const float*)d_in[22];
    const float* wq2  = (const float*)d_in[23];
    const float* wq2b = (const float*)d_in[24];
    const float* wk   = (const float*)d_in[25];
    const float* wkb  = (const float*)d_in[26];
    const float* wv   = (const float*)d_in[27];
    const float* wvb  = (const float*)d_in[28];
    const int*   e1   = (const int*)d_in[29];
    const int*   e2   = (const int*)d_in[30];
    float* out = (float*)d_out;

    cudaFuncSetAttribute(k_pat, cudaFuncAttributeMaxDynamicSharedMemorySize, KP_SMEM * 4);

    k_deg<<<dim3(96, 2), 128>>>(e1, e2);
    k_lin0<<<dim3(24, 2), 256>>>(f1, f2, l0w1, l0b1, l0w2, l0b2);
    for (int l = 0; l < 5; l++) {
        k_agg<<<1728, 256>>>(e1, e2);
        k_mlp<<<dim3(24, 2), 256>>>(gw1, gb1, gw2, gb2, geps, l);
        k_bn<<<dim3(64, 2), 384>>>(gga, gbe, l);
    }
    k_A<<<dim3(6, 24), 256>>>(ged);
    k_h2T<<<576, 256>>>();
    k_pat<<<dim3(384, 12), 256, KP_SMEM * 4>>>(wih, whh, bih, bhh, waw, wab, vat);
    k_ctx<<<dim3(384, 12), 256>>>(wq1, wq1b, wq2, wq2b, wk, wkb, wv, wvb, out);
}

// round 11
// speedup vs baseline: 1.6401x; 1.0570x over previous
#include <cuda_runtime.h>
#include <cuda_bf16.h>
#include <math.h>

#define NN   384
#define EE   3456
#define ENS  3072
#define F3   64
#define KK   32
#define NLAY 6

__device__ float g_h[2][NLAY][NN][F3];
__device__ float g_hcur[2][NN][F3];
__device__ float g_agg[2][NN][F3];
__device__ float g_z[2][NN][F3];
__device__ float g_deg[2][NN];
__device__ float g_AT[NLAY][NN][F3][KK];   // A transposed: [l][i][e][k]
__device__ float g_h2T[NLAY][F3][NN];
__device__ float g_pat[NN][NN][KK];
__device__ float g_X[NLAY][NN][NN][KK];    // stack values, written by k_pat

// ---------------- degrees: distinct dst per src over first 3072 edges -------
__global__ void k_deg(const int* __restrict__ e1, const int* __restrict__ e2) {
    __shared__ unsigned smask[4][12];
    int g = blockIdx.y;
    const int* E = g ? e2 : e1;
    int wid = threadIdx.x >> 5, lane = threadIdx.x & 31;
    int node = blockIdx.x * 4 + wid;
    if (lane < 12) smask[wid][lane] = 0u;
    __syncwarp();
    for (int t = lane; t < ENS; t += 32) {
        if (E[t] == node) {
            int d = E[EE + t];
            atomicOr(&smask[wid][d >> 5], 1u << (d & 31));
        }
    }
    __syncwarp();
    unsigned m = (lane < 12) ? smask[wid][lane] : 0u;
    int cnt = __popc(m);
#pragma unroll
    for (int o = 16; o; o >>= 1) cnt += __shfl_xor_sync(0xffffffffu, cnt, o);
    if (lane == 0) g_deg[g][node] = (float)cnt;
}

// ---------------- lin0: 16 rows per block -----------------------------------
__global__ void k_lin0(const float* __restrict__ f1, const float* __restrict__ f2,
                       const float* __restrict__ w1, const float* __restrict__ b1,
                       const float* __restrict__ w2, const float* __restrict__ b2) {
    int g = blockIdx.y, rt = blockIdx.x;       // 24 row tiles of 16
    const float* F = g ? f2 : f1;
    __shared__ float xs[16][33];
    __shared__ float w1s[33 * 64];
    __shared__ float hid[16 * 64];
    int tid = threadIdx.x;
    for (int idx = tid; idx < 33 * 64; idx += 256) w1s[idx] = w1[idx];
    for (int idx = tid; idx < 16 * 32; idx += 256) xs[idx >> 5][idx & 31] = F[rt * 512 + idx];
    if (tid < 16) xs[tid][32] = g_deg[g][rt * 16 + tid];
    for (int idx = tid; idx < 16 * 64; idx += 256)
        g_agg[g][rt * 16 + (idx >> 6)][idx & 63] = 0.f;
    __syncthreads();
    int c = tid & 63, r0 = tid >> 6;
#pragma unroll 1
    for (int rr = 0; rr < 4; rr++) {
        int r = r0 + rr * 4;
        float acc = b1[c];
#pragma unroll
        for (int d = 0; d < 33; d++) acc += xs[r][d] * w1s[d * 64 + c];
        hid[r * 64 + c] = fmaxf(acc, 0.f);
    }
    __syncthreads();
#pragma unroll 1
    for (int rr = 0; rr < 4; rr++) {
        int r = r0 + rr * 4;
        float acc = b2[c];
#pragma unroll
        for (int m = 0; m < 64; m++) acc += hid[r * 64 + m] * w2[m * 64 + c];
        int row = rt * 16 + r;
        g_h[g][0][row][c] = acc;
        g_hcur[g][row][c] = acc;   // first GIN consumes h0 WITHOUT relu
    }
}

// ---------------- GIN aggregation ------------------------------------------
__global__ void k_agg(const int* __restrict__ e1, const int* __restrict__ e2) {
    int idx = blockIdx.x * 256 + threadIdx.x;          // 2*3456*64 threads
    int c = idx & 63;
    int e = (idx >> 6) % EE;
    int g = idx / (EE * 64);
    const int* E = g ? e2 : e1;
    atomicAdd(&g_agg[g][E[EE + e]][c], g_hcur[g][E[e]][c]);
}

// ---------------- GIN MLP: 16 rows per block --------------------------------
__global__ void k_mlp(const float* __restrict__ gw1, const float* __restrict__ gb1,
                      const float* __restrict__ gw2, const float* __restrict__ gb2,
                      const float* __restrict__ geps, int l) {
    int g = blockIdx.y, rt = blockIdx.x;       // 24 tiles of 16 rows
    __shared__ float zs[16][64];
    __shared__ float ws[64 * 64];
    __shared__ float hid[16 * 64];
    int tid = threadIdx.x;
    float eps1 = 1.f + geps[l];
    const float* w1 = gw1 + l * 4096;
    const float* w2 = gw2 + l * 4096;
    for (int idx = tid; idx < 4096; idx += 256) ws[idx] = w1[idx];
    for (int idx = tid; idx < 1024; idx += 256) {
        int r = idx >> 6, d = idx & 63, row = rt * 16 + r;
        zs[r][d] = eps1 * g_hcur[g][row][d] + g_agg[g][row][d];
    }
    __syncthreads();
    int c = tid & 63, r0 = tid >> 6;
#pragma unroll 1
    for (int rr = 0; rr < 4; rr++) {
        int r = r0 + rr * 4;
        float acc = gb1[l * 64 + c];
#pragma unroll
        for (int d = 0; d < 64; d++) acc += zs[r][d] * ws[d * 64 + c];
        hid[r * 64 + c] = fmaxf(acc, 0.f);
    }
    __syncthreads();
#pragma unroll 1
    for (int rr = 0; rr < 4; rr++) {
        int r = r0 + rr * 4;
        float acc = gb2[l * 64 + c];
#pragma unroll
        for (int m = 0; m < 64; m++) acc += hid[r * 64 + m] * w2[m * 64 + c];
        g_z[g][rt * 16 + r][c] = acc;
    }
}

// ---------------- BatchNorm + relu + zero agg -------------------------------
__global__ void k_bn(const float* __restrict__ gamma, const float* __restrict__ beta, int l) {
    int c = blockIdx.x, g = blockIdx.y, t = threadIdx.x;   // 384 threads
    __shared__ float red[12];
    __shared__ float bc;
    float val = g_z[g][t][c];
    float s = val;
#pragma unroll
    for (int o = 16; o; o >>= 1) s += __shfl_xor_sync(0xffffffffu, s, o);
    if ((t & 31) == 0) red[t >> 5] = s;
    __syncthreads();
    if (t < 32) {
        float v = (t < 12) ? red[t] : 0.f;
#pragma unroll
        for (int o = 16; o; o >>= 1) v += __shfl_xor_sync(0xffffffffu, v, o);
        if (t == 0) bc = v * (1.f / 384.f);
    }
    __syncthreads();
    float mu = bc;
    __syncthreads();
    float d = val - mu;
    float s2 = d * d;
#pragma unroll
    for (int o = 16; o; o >>= 1) s2 += __shfl_xor_sync(0xffffffffu, s2, o);
    if ((t & 31) == 0) red[t >> 5] = s2;
    __syncthreads();
    if (t < 32) {
        float v = (t < 12) ? red[t] : 0.f;
#pragma unroll
        for (int o = 16; o; o >>= 1) v += __shfl_xor_sync(0xffffffffu, v, o);
        if (t == 0) bc = v * (1.f / 384.f);
    }
    __syncthreads();
    float var = bc;
    float norm = d * rsqrtf(var + 1e-5f) * gamma[l * 64 + c] + beta[l * 64 + c];
    g_h[g][l + 1][t][c] = norm;
    g_hcur[g][t][c] = fmaxf(norm, 0.f);
    g_agg[g][t][c] = 0.f;
}

// ---------------- A^T[l,i,e,k] = sum_d h1[l,i,d]*ged[l,k,d,e] ---------------
__global__ void k_A(const float* __restrict__ ged) {
    int l = blockIdx.x, it = blockIdx.y * 16;
    __shared__ float h1s[16][64];
    int tid = threadIdx.x;
    for (int idx = tid; idx < 1024; idx += 256)
        h1s[idx >> 6][idx & 63] = g_h[0][l][it + (idx >> 6)][idx & 63];
    __syncthreads();
    int e = tid & 63, kq = tid >> 6;
#pragma unroll 1
    for (int kk2 = 0; kk2 < 8; kk2++) {
        int k = kq * 8 + kk2;
        float4 a0 = make_float4(0.f, 0.f, 0.f, 0.f);
        float4 a1 = make_float4(0.f, 0.f, 0.f, 0.f);
        float4 a2 = make_float4(0.f, 0.f, 0.f, 0.f);
        float4 a3 = make_float4(0.f, 0.f, 0.f, 0.f);
        const float* mp = ged + ((l * KK + k) * 64) * 64 + e;
#pragma unroll 4
        for (int d = 0; d < 64; d++) {
            float m = mp[d * 64];
            a0.x += h1s[0][d] * m;  a0.y += h1s[1][d] * m;
            a0.z += h1s[2][d] * m;  a0.w += h1s[3][d] * m;
            a1.x += h1s[4][d] * m;  a1.y += h1s[5][d] * m;
            a1.z += h1s[6][d] * m;  a1.w += h1s[7][d] * m;
            a2.x += h1s[8][d] * m;  a2.y += h1s[9][d] * m;
            a2.z += h1s[10][d] * m; a2.w += h1s[11][d] * m;
            a3.x += h1s[12][d] * m; a3.y += h1s[13][d] * m;
            a3.z += h1s[14][d] * m; a3.w += h1s[15][d] * m;
        }
        g_AT[l][it + 0][e][k]  = a0.x;  g_AT[l][it + 1][e][k]  = a0.y;
        g_AT[l][it + 2][e][k]  = a0.z;  g_AT[l][it + 3][e][k]  = a0.w;
        g_AT[l][it + 4][e][k]  = a1.x;  g_AT[l][it + 5][e][k]  = a1.y;
        g_AT[l][it + 6][e][k]  = a1.z;  g_AT[l][it + 7][e][k]  = a1.w;
        g_AT[l][it + 8][e][k]  = a2.x;  g_AT[l][it + 9][e][k]  = a2.y;
        g_AT[l][it + 10][e][k] = a2.z;  g_AT[l][it + 11][e][k] = a2.w;
        g_AT[l][it + 12][e][k] = a3.x;  g_AT[l][it + 13][e][k] = a3.y;
        g_AT[l][it + 14][e][k] = a3.z;  g_AT[l][it + 15][e][k] = a3.w;
    }
}

// ---------------- transpose h2 ----------------------------------------------
__global__ void k_h2T() {
    int idx = blockIdx.x * 256 + threadIdx.x;
    if (idx >= NLAY * 64 * NN) return;
    int l = idx / (64 * NN), rem = idx % (64 * NN);
    int e = rem / NN, j = rem % NN;
    g_h2T[l][e][j] = g_h[1][l][j][e];
}

// ---------------- helpers ---------------------------------------------------
__device__ __forceinline__ float4 shfl4(float4 v, int s) {
    float4 r;
    r.x = __shfl_sync(0xffffffffu, v.x, s);
    r.y = __shfl_sync(0xffffffffu, v.y, s);
    r.z = __shfl_sync(0xffffffffu, v.z, s);
    r.w = __shfl_sync(0xffffffffu, v.w, s);
    return r;
}
__device__ __forceinline__ float sigm_f(float x) { return 1.f / (1.f + __expf(-x)); }
__device__ __forceinline__ float tanh_f(float x) { return 1.f - 2.f / (1.f + __expf(2.f * x)); }
__device__ __forceinline__ float4 set4(float v) { return make_float4(v, v, v, v); }
#define FMA4V(acc, s, v) \
    (acc).x += (s) * (v).x; (acc).y += (s) * (v).y; (acc).z += (s) * (v).z; (acc).w += (s) * (v).w;
#define RED4(v) \
    _Pragma("unroll") \
    for (int o_ = 16; o_; o_ >>= 1) { \
        (v).x += __shfl_xor_sync(0xffffffffu, (v).x, o_); \
        (v).y += __shfl_xor_sync(0xffffffffu, (v).y, o_); \
        (v).z += __shfl_xor_sync(0xffffffffu, (v).z, o_); \
        (v).w += __shfl_xor_sync(0xffffffffu, (v).w, o_); \
    }

// ---------------- phase 1: GRU + layer attention -> g_pat, g_X --------------
// lane = channel k; warp = 8 pairs (two float4 halves a/b). Weight LDS
// amortized over 8 pairs -> ~4.8 FMA per LDS.
// Dynamic SMEM (floats):
//   s_wih 0      (3072)  [m*96+c] transposed
//   s_whh 3072   (3072)
//   s_wa  6144   (1024)  [m*32+kp]
//   s_AT  7168   (2048)  [e*32+k]
//   s_h2  9216   (4096)  [e*64+jl]  block's 64 j
//   s_x   13312  (2048)  [w][m][8]
//   s_h   15360  (2048)
#define KP_SMEM 17408
__global__ void __launch_bounds__(256)
k_pat(const float* __restrict__ wih, const float* __restrict__ whh,
      const float* __restrict__ bih, const float* __restrict__ bhh,
      const float* __restrict__ wattn, const float* __restrict__ wattnb,
      const float* __restrict__ vattn) {
    extern __shared__ float sm[];
    float* s_wih = sm;
    float* s_whh = sm + 3072;
    float* s_wa  = sm + 6144;
    float* s_AT  = sm + 7168;
    float* s_h2  = sm + 9216;
    float* s_x   = sm + 13312;
    float* s_h   = sm + 15360;

    int tid = threadIdx.x, i = blockIdx.x, jb = blockIdx.y;
    int w = tid >> 5, k = tid & 31;
    int j0 = jb * 64 + w * 8;

    for (int idx = tid; idx < 3072; idx += 256) {
        int m = idx / 96, c = idx - m * 96;
        s_wih[idx] = wih[c * 32 + m];
        s_whh[idx] = whh[c * 32 + m];
    }
    for (int idx = tid; idx < 1024; idx += 256) s_wa[idx] = wattn[idx];
    *(float4*)&s_h[(w * 32 + k) * 8]     = set4(0.f);
    *(float4*)&s_h[(w * 32 + k) * 8 + 4] = set4(0.f);

    float bihr = bih[k], bihz = bih[32 + k], bihn = bih[64 + k];
    float bhhr = bhh[k], bhhz = bhh[32 + k], bhhn = bhh[64 + k];
    float wabk = wattnb[k], vk = vattn[k];

    float4 ha = set4(0.f), hb = set4(0.f);
    float4 pacca = set4(0.f), paccb = set4(0.f);
    float4 Ma = set4(-1e30f), Mb = set4(-1e30f);
    float4 Sa = set4(0.f), Sb = set4(0.f);

#pragma unroll 1
    for (int l = 0; l < 6; l++) {
        __syncthreads();
        {
            const float* srcA = &g_AT[l][i][0][0];
            for (int idx = tid; idx < 2048; idx += 256) s_AT[idx] = srcA[idx];
            const float* srcH = &g_h2T[l][0][jb * 64];
            for (int idx = tid; idx < 4096; idx += 256)
                s_h2[idx] = srcH[(idx >> 6) * NN + (idx & 63)];
        }
        __syncthreads();

        // x_k = sum_e A[e][k] * h2[e][j]   (8 pairs)
        float4 xa = set4(0.f), xb = set4(0.f);
#pragma unroll 4
        for (int e = 0; e < 64; e++) {
            float a = s_AT[e * 32 + k];
            float4 hva = *(const float4*)&s_h2[e * 64 + w * 8];
            float4 hvb = *(const float4*)&s_h2[e * 64 + w * 8 + 4];
            FMA4V(xa, a, hva)
            FMA4V(xb, a, hvb)
        }
        __stcg(&g_X[l][i][j0 + 0][k], xa.x);
        __stcg(&g_X[l][i][j0 + 1][k], xa.y);
        __stcg(&g_X[l][i][j0 + 2][k], xa.z);
        __stcg(&g_X[l][i][j0 + 3][k], xa.w);
        __stcg(&g_X[l][i][j0 + 4][k], xb.x);
        __stcg(&g_X[l][i][j0 + 5][k], xb.y);
        __stcg(&g_X[l][i][j0 + 6][k], xb.z);
        __stcg(&g_X[l][i][j0 + 7][k], xb.w);

        __syncwarp();
        *(float4*)&s_x[(w * 32 + k) * 8]     = xa;
        *(float4*)&s_x[(w * 32 + k) * 8 + 4] = xb;
        __syncwarp();

        // GRU gates: per m, 6 scalar weight LDS + 4 LDS.128 for 48 FMA
        float4 aira = set4(bihr), airb = set4(bihr);
        float4 aiza = set4(bihz), aizb = set4(bihz);
        float4 aina = set4(bihn), ainb = set4(bihn);
        float4 ahra = set4(bhhr), ahrb = set4(bhhr);
        float4 ahza = set4(bhhz), ahzb = set4(bhhz);
        float4 ahna = set4(bhhn), ahnb = set4(bhhn);
#pragma unroll 4
        for (int m = 0; m < 32; m++) {
            float4 xma = *(const float4*)&s_x[(w * 32 + m) * 8];
            float4 xmb = *(const float4*)&s_x[(w * 32 + m) * 8 + 4];
            float4 hma = *(const float4*)&s_h[(w * 32 + m) * 8];
            float4 hmb = *(const float4*)&s_h[(w * 32 + m) * 8 + 4];
            float wir = s_wih[m * 96 + k], wiz = s_wih[m * 96 + 32 + k], win = s_wih[m * 96 + 64 + k];
            float whr = s_whh[m * 96 + k], whz = s_whh[m * 96 + 32 + k], whn = s_whh[m * 96 + 64 + k];
            FMA4V(aira, wir, xma) FMA4V(airb, wir, xmb)
            FMA4V(aiza, wiz, xma) FMA4V(aizb, wiz, xmb)
            FMA4V(aina, win, xma) FMA4V(ainb, win, xmb)
            FMA4V(ahra, whr, hma) FMA4V(ahrb, whr, hmb)
            FMA4V(ahza, whz, hma) FMA4V(ahzb, whz, hmb)
            FMA4V(ahna, whn, hma) FMA4V(ahnb, whn, hmb)
        }
        {
            float r0 = sigm_f(aira.x + ahra.x), r1 = sigm_f(aira.y + ahra.y);
            float r2 = sigm_f(aira.z + ahra.z), r3 = sigm_f(aira.w + ahra.w);
            float z0 = sigm_f(aiza.x + ahza.x), z1 = sigm_f(aiza.y + ahza.y);
            float z2 = sigm_f(aiza.z + ahza.z), z3 = sigm_f(aiza.w + ahza.w);
            float n0 = tanh_f(aina.x + r0 * ahna.x), n1 = tanh_f(aina.y + r1 * ahna.y);
            float n2 = tanh_f(aina.z + r2 * ahna.z), n3 = tanh_f(aina.w + r3 * ahna.w);
            ha.x = (1.f - z0) * n0 + z0 * ha.x;
            ha.y = (1.f - z1) * n1 + z1 * ha.y;
            ha.z = (1.f - z2) * n2 + z2 * ha.z;
            ha.w = (1.f - z3) * n3 + z3 * ha.w;
        }
        {
            float r0 = sigm_f(airb.x + ahrb.x), r1 = sigm_f(airb.y + ahrb.y);
            float r2 = sigm_f(airb.z + ahrb.z), r3 = sigm_f(airb.w + ahrb.w);
            float z0 = sigm_f(aizb.x + ahzb.x), z1 = sigm_f(aizb.y + ahzb.y);
            float z2 = sigm_f(aizb.z + ahzb.z), z3 = sigm_f(aizb.w + ahzb.w);
            float n0 = tanh_f(ainb.x + r0 * ahnb.x), n1 = tanh_f(ainb.y + r1 * ahnb.y);
            float n2 = tanh_f(ainb.z + r2 * ahnb.z), n3 = tanh_f(ainb.w + r3 * ahnb.w);
            hb.x = (1.f - z0) * n0 + z0 * hb.x;
            hb.y = (1.f - z1) * n1 + z1 * hb.y;
            hb.z = (1.f - z2) * n2 + z2 * hb.z;
            hb.w = (1.f - z3) * n3 + z3 * hb.w;
        }

        __syncwarp();
        *(float4*)&s_h[(w * 32 + k) * 8]     = ha;
        *(float4*)&s_h[(w * 32 + k) * 8 + 4] = hb;
        __syncwarp();

        // attention score
        float4 ta = set4(wabk), tb = set4(wabk);
#pragma unroll 4
        for (int m = 0; m < 32; m++) {
            float4 hma = *(const float4*)&s_h[(w * 32 + m) * 8];
            float4 hmb = *(const float4*)&s_h[(w * 32 + m) * 8 + 4];
            float wv_ = s_wa[m * 32 + k];
            FMA4V(ta, wv_, hma)
            FMA4V(tb, wv_, hmb)
        }
        ta.x = tanh_f(ta.x) * vk; ta.y = tanh_f(ta.y) * vk;
        ta.z = tanh_f(ta.z) * vk; ta.w = tanh_f(ta.w) * vk;
        tb.x = tanh_f(tb.x) * vk; tb.y = tanh_f(tb.y) * vk;
        tb.z = tanh_f(tb.z) * vk; tb.w = tanh_f(tb.w) * vk;
        RED4(ta)
        RED4(tb)
        {
            float4 nm;
            nm.x = fmaxf(Ma.x, ta.x); nm.y = fmaxf(Ma.y, ta.y);
            nm.z = fmaxf(Ma.z, ta.z); nm.w = fmaxf(Ma.w, ta.w);
            float f0x = __expf(Ma.x - nm.x), f0y = __expf(Ma.y - nm.y);
            float f0z = __expf(Ma.z - nm.z), f0w = __expf(Ma.w - nm.w);
            float px = __expf(ta.x - nm.x), py = __expf(ta.y - nm.y);
            float pz = __expf(ta.z - nm.z), pw = __expf(ta.w - nm.w);
            Sa.x = Sa.x * f0x + px; Sa.y = Sa.y * f0y + py;
            Sa.z = Sa.z * f0z + pz; Sa.w = Sa.w * f0w + pw;
            pacca.x = pacca.x * f0x + px * ha.x;
            pacca.y = pacca.y * f0y + py * ha.y;
            pacca.z = pacca.z * f0z + pz * ha.z;
            pacca.w = pacca.w * f0w + pw * ha.w;
            Ma = nm;
        }
        {
            float4 nm;
            nm.x = fmaxf(Mb.x, tb.x); nm.y = fmaxf(Mb.y, tb.y);
            nm.z = fmaxf(Mb.z, tb.z); nm.w = fmaxf(Mb.w, tb.w);
            float f0x = __expf(Mb.x - nm.x), f0y = __expf(Mb.y - nm.y);
            float f0z = __expf(Mb.z - nm.z), f0w = __expf(Mb.w - nm.w);
            float px = __expf(tb.x - nm.x), py = __expf(tb.y - nm.y);
            float pz = __expf(tb.z - nm.z), pw = __expf(tb.w - nm.w);
            Sb.x = Sb.x * f0x + px; Sb.y = Sb.y * f0y + py;
            Sb.z = Sb.z * f0z + pz; Sb.w = Sb.w * f0w + pw;
            paccb.x = paccb.x * f0x + px * hb.x;
            paccb.y = paccb.y * f0y + py * hb.y;
            paccb.z = paccb.z * f0z + pz * hb.z;
            paccb.w = paccb.w * f0w + pw * hb.w;
            Mb = nm;
        }
    }
    g_pat[i][j0 + 0][k] = pacca.x / Sa.x;
    g_pat[i][j0 + 1][k] = pacca.y / Sa.y;
    g_pat[i][j0 + 2][k] = pacca.z / Sa.z;
    g_pat[i][j0 + 3][k] = pacca.w / Sa.w;
    g_pat[i][j0 + 4][k] = paccb.x / Sb.x;
    g_pat[i][j0 + 5][k] = paccb.y / Sb.y;
    g_pat[i][j0 + 6][k] = paccb.z / Sb.z;
    g_pat[i][j0 + 7][k] = paccb.w / Sb.w;
}

// ---------------- phase 2: q/k/v + layer softmax -> context -----------------
__global__ void __launch_bounds__(256)
k_ctx(const float* __restrict__ wq1, const float* __restrict__ wq1b,
      const float* __restrict__ wq2, const float* __restrict__ wq2b,
      const float* __restrict__ wk, const float* __restrict__ wkb,
      const float* __restrict__ wv, const float* __restrict__ wvb,
      float* __restrict__ out) {
    __shared__ float s_wq1[1024];
    __shared__ float s_wq2[1024];
    __shared__ float s_wkT[1024];
    __shared__ float s_wv[1024];

    int tid = threadIdx.x, i = blockIdx.x, jb = blockIdx.y;
    int w = tid >> 5, k = tid & 31;
    int j0 = jb * 32 + w * 4;

    for (int idx = tid; idx < 1024; idx += 256) {
        int p = idx >> 5, e = idx & 31;
        s_wq1[idx] = wq1[idx];
        s_wq2[idx] = wq2[idx];
        s_wv[idx]  = wv[idx];
        s_wkT[idx] = wk[e * 32 + p];
    }
    float wq1bk = wq1b[k], wq2bk = wq2b[k], wkbk = wkb[k], wvbk = wvb[k];
    __syncthreads();

    float4 pat;
    pat.x = g_pat[i][j0 + 0][k];
    pat.y = g_pat[i][j0 + 1][k];
    pat.z = g_pat[i][j0 + 2][k];
    pat.w = g_pat[i][j0 + 3][k];

    float4 t1 = set4(wq1bk);
#pragma unroll 4
    for (int m = 0; m < 32; m++) {
        float4 pm = shfl4(pat, m);
        float wv_ = s_wq1[m * 32 + k];
        FMA4V(t1, wv_, pm)
    }
    t1.x = fmaxf(t1.x, 0.f); t1.y = fmaxf(t1.y, 0.f);
    t1.z = fmaxf(t1.z, 0.f); t1.w = fmaxf(t1.w, 0.f);

    float4 q4 = set4(wq2bk);
#pragma unroll 4
    for (int m = 0; m < 32; m++) {
        float4 tm = shfl4(t1, m);
        float wv_ = s_wq2[m * 32 + k];
        FMA4V(q4, wv_, tm)
    }

    float4 qk4 = set4(0.f);
#pragma unroll 4
    for (int p = 0; p < 32; p++) {
        float4 qm = shfl4(q4, p);
        float wv_ = s_wkT[p * 32 + k];
        FMA4V(qk4, wv_, qm)
    }
    float4 qb4;
    qb4.x = q4.x * wkbk; qb4.y = q4.y * wkbk; qb4.z = q4.z * wkbk; qb4.w = q4.w * wkbk;
    RED4(qb4)

    float4 sacc = set4(0.f), M4 = set4(-1e30f), S4 = set4(0.f);
#pragma unroll 1
    for (int l = 0; l < 6; l++) {
        float4 x4;
        x4.x = g_X[l][i][j0 + 0][k];
        x4.y = g_X[l][i][j0 + 1][k];
        x4.z = g_X[l][i][j0 + 2][k];
        x4.w = g_X[l][i][j0 + 3][k];

        float4 s4;
        s4.x = qk4.x * x4.x; s4.y = qk4.y * x4.y; s4.z = qk4.z * x4.z; s4.w = qk4.w * x4.w;
        RED4(s4)
        s4.x = (s4.x + qb4.x) * 0.17677669529663687f;
        s4.y = (s4.y + qb4.y) * 0.17677669529663687f;
        s4.z = (s4.z + qb4.z) * 0.17677669529663687f;
        s4.w = (s4.w + qb4.w) * 0.17677669529663687f;

        float4 nm4;
        nm4.x = fmaxf(M4.x, s4.x); nm4.y = fmaxf(M4.y, s4.y);
        nm4.z = fmaxf(M4.z, s4.z); nm4.w = fmaxf(M4.w, s4.w);
        float f0x = __expf(M4.x - nm4.x), f0y = __expf(M4.y - nm4.y);
        float f0z = __expf(M4.z - nm4.z), f0w = __expf(M4.w - nm4.w);
        float px = __expf(s4.x - nm4.x), py = __expf(s4.y - nm4.y);
        float pz = __expf(s4.z - nm4.z), pw = __expf(s4.w - nm4.w);
        S4.x = S4.x * f0x + px; S4.y = S4.y * f0y + py;
        S4.z = S4.z * f0z + pz; S4.w = S4.w * f0w + pw;
        sacc.x = sacc.x * f0x + px * x4.x;
        sacc.y = sacc.y * f0y + py * x4.y;
        sacc.z = sacc.z * f0z + pz * x4.z;
        sacc.w = sacc.w * f0w + pw * x4.w;
        M4 = nm4;
    }
    sacc.x /= S4.x; sacc.y /= S4.y; sacc.z /= S4.z; sacc.w /= S4.w;

    float4 c4 = set4(wvbk);
#pragma unroll 4
    for (int p = 0; p < 32; p++) {
        float4 sm4 = shfl4(sacc, p);
        float wv_ = s_wv[p * 32 + k];
        FMA4V(c4, wv_, sm4)
    }
    out[((size_t)i * NN + j0 + 0) * KK + k] = c4.x;
    out[((size_t)i * NN + j0 + 1) * KK + k] = c4.y;
    out[((size_t)i * NN + j0 + 2) * KK + k] = c4.z;
    out[((size_t)i * NN + j0 + 3) * KK + k] = c4.w;
}

// ---------------- host ------------------------------------------------------
extern "C" void kernel_launch(void* const* d_in, const int* in_sizes, int n_in,
                              void* d_out, int out_size) {
    const float* f1   = (const float*)d_in[0];
    const float* f2   = (const float*)d_in[1];
    const float* l0w1 = (const float*)d_in[2];
    const float* l0b1 = (const float*)d_in[3];
    const float* l0w2 = (const float*)d_in[4];
    const float* l0b2 = (const float*)d_in[5];
    const float* geps = (const float*)d_in[6];
    const float* gw1  = (const float*)d_in[7];
    const float* gb1  = (const float*)d_in[8];
    const float* gw2  = (const float*)d_in[9];
    const float* gb2  = (const float*)d_in[10];
    const float* gga  = (const float*)d_in[11];
    const float* gbe  = (const float*)d_in[12];
    const float* ged  = (const float*)d_in[13];
    const float* wih  = (const float*)d_in[14];
    const float* whh  = (const float*)d_in[15];
    const float* bih  = (const float*)d_in[16];
    const float* bhh  = (const float*)d_in[17];
    const float* waw  = (const float*)d_in[18];
    const float* wab  = (const float*)d_in[19];
    const float* vat  = (const float*)d_in[20];
    const float* wq1  = (const float*)d_in[21];
    const float* wq1b = (const float*)d_in[22];
    const float* wq2  = (const float*)d_in[23];
    const float* wq2b = (const float*)d_in[24];
    const float* wk   = (const float*)d_in[25];
    const float* wkb  = (const float*)d_in[26];
    const float* wv   = (const float*)d_in[27];
    const float* wvb  = (const float*)d_in[28];
    const int*   e1   = (const int*)d_in[29];
    const int*   e2   = (const int*)d_in[30];
    float* out = (float*)d_out;

    cudaFuncSetAttribute(k_pat, cudaFuncAttributeMaxDynamicSharedMemorySize, KP_SMEM * 4);

    k_deg<<<dim3(96, 2), 128>>>(e1, e2);
    k_lin0<<<dim3(24, 2), 256>>>(f1, f2, l0w1, l0b1, l0w2, l0b2);
    for (int l = 0; l < 5; l++) {
        k_agg<<<1728, 256>>>(e1, e2);
        k_mlp<<<dim3(24, 2), 256>>>(gw1, gb1, gw2, gb2, geps, l);
        k_bn<<<dim3(64, 2), 384>>>(gga, gbe, l);
    }
    k_A<<<dim3(6, 24), 256>>>(ged);
    k_h2T<<<576, 256>>>();
    k_pat<<<dim3(384, 6), 256, KP_SMEM * 4>>>(wih, whh, bih, bhh, waw, wab, vat);
    k_ctx<<<dim3(384, 12), 256>>>(wq1, wq1b, wq2, wq2b, wk, wkb, wv, wvb, out);
}

// round 12
// speedup vs baseline: 1.7037x; 1.0388x over previous
#include <cuda_runtime.h>
#include <cuda_bf16.h>
#include <math.h>

#define NN   384
#define EE   3456
#define ENS  3072
#define F3   64
#define KK   32
#define NLAY 6
typedef unsigned long long U64;

__device__ float g_h[2][NLAY][NN][F3];
__device__ float g_hcur[2][NN][F3];
__device__ float g_agg[2][NN][F3];
__device__ float g_z[2][NN][F3];
__device__ float g_deg[2][NN];
__device__ float g_AT[NLAY][NN][F3][KK];   // A transposed: [l][i][e][k]
__device__ float g_h2T[NLAY][F3][NN];
__device__ float g_pat[NN][NN][KK];
__device__ float g_X[NLAY][NN][NN][KK];    // stack values, written by k_pat

// ---------------- degrees: distinct dst per src over first 3072 edges -------
__global__ void k_deg(const int* __restrict__ e1, const int* __restrict__ e2) {
    __shared__ unsigned smask[4][12];
    int g = blockIdx.y;
    const int* E = g ? e2 : e1;
    int wid = threadIdx.x >> 5, lane = threadIdx.x & 31;
    int node = blockIdx.x * 4 + wid;
    if (lane < 12) smask[wid][lane] = 0u;
    __syncwarp();
    for (int t = lane; t < ENS; t += 32) {
        if (E[t] == node) {
            int d = E[EE + t];
            atomicOr(&smask[wid][d >> 5], 1u << (d & 31));
        }
    }
    __syncwarp();
    unsigned m = (lane < 12) ? smask[wid][lane] : 0u;
    int cnt = __popc(m);
#pragma unroll
    for (int o = 16; o; o >>= 1) cnt += __shfl_xor_sync(0xffffffffu, cnt, o);
    if (lane == 0) g_deg[g][node] = (float)cnt;
}

// ---------------- lin0: 16 rows per block -----------------------------------
__global__ void k_lin0(const float* __restrict__ f1, const float* __restrict__ f2,
                       const float* __restrict__ w1, const float* __restrict__ b1,
                       const float* __restrict__ w2, const float* __restrict__ b2) {
    int g = blockIdx.y, rt = blockIdx.x;       // 24 row tiles of 16
    const float* F = g ? f2 : f1;
    __shared__ float xs[16][33];
    __shared__ float w1s[33 * 64];
    __shared__ float hid[16 * 64];
    int tid = threadIdx.x;
    for (int idx = tid; idx < 33 * 64; idx += 256) w1s[idx] = w1[idx];
    for (int idx = tid; idx < 16 * 32; idx += 256) xs[idx >> 5][idx & 31] = F[rt * 512 + idx];
    if (tid < 16) xs[tid][32] = g_deg[g][rt * 16 + tid];
    for (int idx = tid; idx < 16 * 64; idx += 256)
        g_agg[g][rt * 16 + (idx >> 6)][idx & 63] = 0.f;
    __syncthreads();
    int c = tid & 63, r0 = tid >> 6;
#pragma unroll 1
    for (int rr = 0; rr < 4; rr++) {
        int r = r0 + rr * 4;
        float acc = b1[c];
#pragma unroll
        for (int d = 0; d < 33; d++) acc += xs[r][d] * w1s[d * 64 + c];
        hid[r * 64 + c] = fmaxf(acc, 0.f);
    }
    __syncthreads();
#pragma unroll 1
    for (int rr = 0; rr < 4; rr++) {
        int r = r0 + rr * 4;
        float acc = b2[c];
#pragma unroll
        for (int m = 0; m < 64; m++) acc += hid[r * 64 + m] * w2[m * 64 + c];
        int row = rt * 16 + r;
        g_h[g][0][row][c] = acc;
        g_hcur[g][row][c] = acc;   // first GIN consumes h0 WITHOUT relu
    }
}

// ---------------- GIN aggregation ------------------------------------------
__global__ void k_agg(const int* __restrict__ e1, const int* __restrict__ e2) {
    int idx = blockIdx.x * 256 + threadIdx.x;          // 2*3456*64 threads
    int c = idx & 63;
    int e = (idx >> 6) % EE;
    int g = idx / (EE * 64);
    const int* E = g ? e2 : e1;
    atomicAdd(&g_agg[g][E[EE + e]][c], g_hcur[g][E[e]][c]);
}

// ---------------- GIN MLP: 16 rows per block --------------------------------
__global__ void k_mlp(const float* __restrict__ gw1, const float* __restrict__ gb1,
                      const float* __restrict__ gw2, const float* __restrict__ gb2,
                      const float* __restrict__ geps, int l) {
    int g = blockIdx.y, rt = blockIdx.x;       // 24 tiles of 16 rows
    __shared__ float zs[16][64];
    __shared__ float ws[64 * 64];
    __shared__ float hid[16 * 64];
    int tid = threadIdx.x;
    float eps1 = 1.f + geps[l];
    const float* w1 = gw1 + l * 4096;
    const float* w2 = gw2 + l * 4096;
    for (int idx = tid; idx < 4096; idx += 256) ws[idx] = w1[idx];
    for (int idx = tid; idx < 1024; idx += 256) {
        int r = idx >> 6, d = idx & 63, row = rt * 16 + r;
        zs[r][d] = eps1 * g_hcur[g][row][d] + g_agg[g][row][d];
    }
    __syncthreads();
    int c = tid & 63, r0 = tid >> 6;
#pragma unroll 1
    for (int rr = 0; rr < 4; rr++) {
        int r = r0 + rr * 4;
        float acc = gb1[l * 64 + c];
#pragma unroll
        for (int d = 0; d < 64; d++) acc += zs[r][d] * ws[d * 64 + c];
        hid[r * 64 + c] = fmaxf(acc, 0.f);
    }
    __syncthreads();
#pragma unroll 1
    for (int rr = 0; rr < 4; rr++) {
        int r = r0 + rr * 4;
        float acc = gb2[l * 64 + c];
#pragma unroll
        for (int m = 0; m < 64; m++) acc += hid[r * 64 + m] * w2[m * 64 + c];
        g_z[g][rt * 16 + r][c] = acc;
    }
}

// ---------------- BatchNorm + relu + zero agg -------------------------------
__global__ void k_bn(const float* __restrict__ gamma, const float* __restrict__ beta, int l) {
    int c = blockIdx.x, g = blockIdx.y, t = threadIdx.x;   // 384 threads
    __shared__ float red[12];
    __shared__ float bc;
    float val = g_z[g][t][c];
    float s = val;
#pragma unroll
    for (int o = 16; o; o >>= 1) s += __shfl_xor_sync(0xffffffffu, s, o);
    if ((t & 31) == 0) red[t >> 5] = s;
    __syncthreads();
    if (t < 32) {
        float v = (t < 12) ? red[t] : 0.f;
#pragma unroll
        for (int o = 16; o; o >>= 1) v += __shfl_xor_sync(0xffffffffu, v, o);
        if (t == 0) bc = v * (1.f / 384.f);
    }
    __syncthreads();
    float mu = bc;
    __syncthreads();
    float d = val - mu;
    float s2 = d * d;
#pragma unroll
    for (int o = 16; o; o >>= 1) s2 += __shfl_xor_sync(0xffffffffu, s2, o);
    if ((t & 31) == 0) red[t >> 5] = s2;
    __syncthreads();
    if (t < 32) {
        float v = (t < 12) ? red[t] : 0.f;
#pragma unroll
        for (int o = 16; o; o >>= 1) v += __shfl_xor_sync(0xffffffffu, v, o);
        if (t == 0) bc = v * (1.f / 384.f);
    }
    __syncthreads();
    float var = bc;
    float norm = d * rsqrtf(var + 1e-5f) * gamma[l * 64 + c] + beta[l * 64 + c];
    g_h[g][l + 1][t][c] = norm;
    g_hcur[g][t][c] = fmaxf(norm, 0.f);
    g_agg[g][t][c] = 0.f;
}

// ---------------- A^T[l,i,e,k] = sum_d h1[l,i,d]*ged[l,k,d,e] ---------------
__global__ void k_A(const float* __restrict__ ged) {
    int l = blockIdx.x, it = blockIdx.y * 16;
    __shared__ float h1s[16][64];
    int tid = threadIdx.x;
    for (int idx = tid; idx < 1024; idx += 256)
        h1s[idx >> 6][idx & 63] = g_h[0][l][it + (idx >> 6)][idx & 63];
    __syncthreads();
    int e = tid & 63, kq = tid >> 6;
#pragma unroll 1
    for (int kk2 = 0; kk2 < 8; kk2++) {
        int k = kq * 8 + kk2;
        float4 a0 = make_float4(0.f, 0.f, 0.f, 0.f);
        float4 a1 = make_float4(0.f, 0.f, 0.f, 0.f);
        float4 a2 = make_float4(0.f, 0.f, 0.f, 0.f);
        float4 a3 = make_float4(0.f, 0.f, 0.f, 0.f);
        const float* mp = ged + ((l * KK + k) * 64) * 64 + e;
#pragma unroll 4
        for (int d = 0; d < 64; d++) {
            float m = mp[d * 64];
            a0.x += h1s[0][d] * m;  a0.y += h1s[1][d] * m;
            a0.z += h1s[2][d] * m;  a0.w += h1s[3][d] * m;
            a1.x += h1s[4][d] * m;  a1.y += h1s[5][d] * m;
            a1.z += h1s[6][d] * m;  a1.w += h1s[7][d] * m;
            a2.x += h1s[8][d] * m;  a2.y += h1s[9][d] * m;
            a2.z += h1s[10][d] * m; a2.w += h1s[11][d] * m;
            a3.x += h1s[12][d] * m; a3.y += h1s[13][d] * m;
            a3.z += h1s[14][d] * m; a3.w += h1s[15][d] * m;
        }
        g_AT[l][it + 0][e][k]  = a0.x;  g_AT[l][it + 1][e][k]  = a0.y;
        g_AT[l][it + 2][e][k]  = a0.z;  g_AT[l][it + 3][e][k]  = a0.w;
        g_AT[l][it + 4][e][k]  = a1.x;  g_AT[l][it + 5][e][k]  = a1.y;
        g_AT[l][it + 6][e][k]  = a1.z;  g_AT[l][it + 7][e][k]  = a1.w;
        g_AT[l][it + 8][e][k]  = a2.x;  g_AT[l][it + 9][e][k]  = a2.y;
        g_AT[l][it + 10][e][k] = a2.z;  g_AT[l][it + 11][e][k] = a2.w;
        g_AT[l][it + 12][e][k] = a3.x;  g_AT[l][it + 13][e][k] = a3.y;
        g_AT[l][it + 14][e][k] = a3.z;  g_AT[l][it + 15][e][k] = a3.w;
    }
}

// ---------------- transpose h2 ----------------------------------------------
__global__ void k_h2T() {
    int idx = blockIdx.x * 256 + threadIdx.x;
    if (idx >= NLAY * 64 * NN) return;
    int l = idx / (64 * NN), rem = idx % (64 * NN);
    int e = rem / NN, j = rem % NN;
    g_h2T[l][e][j] = g_h[1][l][j][e];
}

// ---------------- helpers ---------------------------------------------------
__device__ __forceinline__ float4 shfl4(float4 v, int s) {
    float4 r;
    r.x = __shfl_sync(0xffffffffu, v.x, s);
    r.y = __shfl_sync(0xffffffffu, v.y, s);
    r.z = __shfl_sync(0xffffffffu, v.z, s);
    r.w = __shfl_sync(0xffffffffu, v.w, s);
    return r;
}
__device__ __forceinline__ float sigm_f(float x) { return 1.f / (1.f + __expf(-x)); }
__device__ __forceinline__ float tanh_f(float x) { return 1.f - 2.f / (1.f + __expf(2.f * x)); }
__device__ __forceinline__ float4 set4(float v) { return make_float4(v, v, v, v); }
#define FMA4V(acc, s, v) \
    (acc).x += (s) * (v).x; (acc).y += (s) * (v).y; (acc).z += (s) * (v).z; (acc).w += (s) * (v).w;
#define RED4(v) \
    _Pragma("unroll") \
    for (int o_ = 16; o_; o_ >>= 1) { \
        (v).x += __shfl_xor_sync(0xffffffffu, (v).x, o_); \
        (v).y += __shfl_xor_sync(0xffffffffu, (v).y, o_); \
        (v).z += __shfl_xor_sync(0xffffffffu, (v).z, o_); \
        (v).w += __shfl_xor_sync(0xffffffffu, (v).w, o_); \
    }

// packed f32x2 helpers (sm_100+): 1 instruction = 2 fp32 FMAs
__device__ __forceinline__ U64 pk2(float v) {
    U64 r; asm("mov.b64 %0, {%1, %2};" : "=l"(r) : "f"(v), "f"(v)); return r;
}
__device__ __forceinline__ void fma2(U64& d, U64 a, U64 b) {
    asm("fma.rn.f32x2 %0, %1, %2, %0;" : "+l"(d) : "l"(a), "l"(b));
}
__device__ __forceinline__ void upk(U64 v, float& lo, float& hi) {
    asm("mov.b64 {%0, %1}, %2;" : "=f"(lo), "=f"(hi) : "l"(v));
}
// process 2 pairs of GRU gates from packed accumulators
#define GRU2(AIR, AIZ, AIN, AHR, AHZ, AHN, H0, H1) do {                      \
    float ir0, ir1, iz0, iz1, in0, in1, hr0, hr1, hz0, hz1, hn0, hn1;        \
    upk(AIR, ir0, ir1); upk(AIZ, iz0, iz1); upk(AIN, in0, in1);              \
    upk(AHR, hr0, hr1); upk(AHZ, hz0, hz1); upk(AHN, hn0, hn1);              \
    float r0_ = sigm_f(ir0 + hr0), r1_ = sigm_f(ir1 + hr1);                  \
    float z0_ = sigm_f(iz0 + hz0), z1_ = sigm_f(iz1 + hz1);                  \
    float n0_ = tanh_f(in0 + r0_ * hn0), n1_ = tanh_f(in1 + r1_ * hn1);      \
    H0 = (1.f - z0_) * n0_ + z0_ * H0;                                       \
    H1 = (1.f - z1_) * n1_ + z1_ * H1;                                       \
} while (0)

// ---------------- phase 1: GRU + layer attention -> g_pat, g_X --------------
// lane = channel k; warp = 8 pairs. Hot loops use fma.rn.f32x2 (2 FMA/instr).
// Dynamic SMEM (floats):
//   s_wih 0      (3072)  [m*96+c] transposed
//   s_whh 3072   (3072)
//   s_wa  6144   (1024)  [m*32+kp]
//   s_AT  7168   (2048)  [e*32+k]
//   s_h2  9216   (4096)  [e*64+jl]  block's 64 j
//   s_x   13312  (2048)  [w][m][8]
//   s_h   15360  (2048)
#define KP_SMEM 17408
__global__ void __launch_bounds__(256)
k_pat(const float* __restrict__ wih, const float* __restrict__ whh,
      const float* __restrict__ bih, const float* __restrict__ bhh,
      const float* __restrict__ wattn, const float* __restrict__ wattnb,
      const float* __restrict__ vattn) {
    extern __shared__ float sm[];
    float* s_wih = sm;
    float* s_whh = sm + 3072;
    float* s_wa  = sm + 6144;
    float* s_AT  = sm + 7168;
    float* s_h2  = sm + 9216;
    float* s_x   = sm + 13312;
    float* s_h   = sm + 15360;

    int tid = threadIdx.x, i = blockIdx.x, jb = blockIdx.y;
    int w = tid >> 5, k = tid & 31;
    int j0 = jb * 64 + w * 8;

    for (int idx = tid; idx < 3072; idx += 256) {
        int m = idx / 96, c = idx - m * 96;
        s_wih[idx] = wih[c * 32 + m];
        s_whh[idx] = whh[c * 32 + m];
    }
    for (int idx = tid; idx < 1024; idx += 256) s_wa[idx] = wattn[idx];
    *(float4*)&s_h[(w * 32 + k) * 8]     = set4(0.f);
    *(float4*)&s_h[(w * 32 + k) * 8 + 4] = set4(0.f);

    float bihr = bih[k], bihz = bih[32 + k], bihn = bih[64 + k];
    float bhhr = bhh[k], bhhz = bhh[32 + k], bhhn = bhh[64 + k];
    float wabk = wattnb[k], vk = vattn[k];

    float4 ha = set4(0.f), hb = set4(0.f);
    float4 pacca = set4(0.f), paccb = set4(0.f);
    float4 Ma = set4(-1e30f), Mb = set4(-1e30f);
    float4 Sa = set4(0.f), Sb = set4(0.f);

#pragma unroll 1
    for (int l = 0; l < 6; l++) {
        __syncthreads();
        {
            const float* srcA = &g_AT[l][i][0][0];
            for (int idx = tid; idx < 2048; idx += 256) s_AT[idx] = srcA[idx];
            const float* srcH = &g_h2T[l][0][jb * 64];
            for (int idx = tid; idx < 4096; idx += 256)
                s_h2[idx] = srcH[(idx >> 6) * NN + (idx & 63)];
        }
        __syncthreads();

        // x_k = sum_e A[e][k] * h2[e][j]  — packed: 4 fma2/e instead of 8 FMA
        U64 xq0 = 0ull, xq1 = 0ull, xq2 = 0ull, xq3 = 0ull;
#pragma unroll 4
        for (int e = 0; e < 64; e++) {
            U64 a2 = pk2(s_AT[e * 32 + k]);
            ulonglong2 hA = *(const ulonglong2*)&s_h2[e * 64 + w * 8];
            ulonglong2 hB = *(const ulonglong2*)&s_h2[e * 64 + w * 8 + 4];
            fma2(xq0, a2, hA.x); fma2(xq1, a2, hA.y);
            fma2(xq2, a2, hB.x); fma2(xq3, a2, hB.y);
        }
        float4 xa, xb;
        upk(xq0, xa.x, xa.y); upk(xq1, xa.z, xa.w);
        upk(xq2, xb.x, xb.y); upk(xq3, xb.z, xb.w);
        __stcg(&g_X[l][i][j0 + 0][k], xa.x);
        __stcg(&g_X[l][i][j0 + 1][k], xa.y);
        __stcg(&g_X[l][i][j0 + 2][k], xa.z);
        __stcg(&g_X[l][i][j0 + 3][k], xa.w);
        __stcg(&g_X[l][i][j0 + 4][k], xb.x);
        __stcg(&g_X[l][i][j0 + 5][k], xb.y);
        __stcg(&g_X[l][i][j0 + 6][k], xb.z);
        __stcg(&g_X[l][i][j0 + 7][k], xb.w);

        __syncwarp();
        *(float4*)&s_x[(w * 32 + k) * 8]     = xa;
        *(float4*)&s_x[(w * 32 + k) * 8 + 4] = xb;
        __syncwarp();

        // GRU gates: per m, 6 weight LDS + 6 pk2 + 4 LDS.128 + 24 fma2 (48 MAC)
        U64 air0 = pk2(bihr), air1 = air0, air2 = air0, air3 = air0;
        U64 aiz0 = pk2(bihz), aiz1 = aiz0, aiz2 = aiz0, aiz3 = aiz0;
        U64 ain0 = pk2(bihn), ain1 = ain0, ain2 = ain0, ain3 = ain0;
        U64 ahr0 = pk2(bhhr), ahr1 = ahr0, ahr2 = ahr0, ahr3 = ahr0;
        U64 ahz0 = pk2(bhhz), ahz1 = ahz0, ahz2 = ahz0, ahz3 = ahz0;
        U64 ahn0 = pk2(bhhn), ahn1 = ahn0, ahn2 = ahn0, ahn3 = ahn0;
#pragma unroll 4
        for (int m = 0; m < 32; m++) {
            ulonglong2 xA = *(const ulonglong2*)&s_x[(w * 32 + m) * 8];
            ulonglong2 xB = *(const ulonglong2*)&s_x[(w * 32 + m) * 8 + 4];
            ulonglong2 hA = *(const ulonglong2*)&s_h[(w * 32 + m) * 8];
            ulonglong2 hB = *(const ulonglong2*)&s_h[(w * 32 + m) * 8 + 4];
            U64 wir = pk2(s_wih[m * 96 + k]);
            U64 wiz = pk2(s_wih[m * 96 + 32 + k]);
            U64 win = pk2(s_wih[m * 96 + 64 + k]);
            U64 whr = pk2(s_whh[m * 96 + k]);
            U64 whz = pk2(s_whh[m * 96 + 32 + k]);
            U64 whn = pk2(s_whh[m * 96 + 64 + k]);
            fma2(air0, wir, xA.x); fma2(air1, wir, xA.y); fma2(air2, wir, xB.x); fma2(air3, wir, xB.y);
            fma2(aiz0, wiz, xA.x); fma2(aiz1, wiz, xA.y); fma2(aiz2, wiz, xB.x); fma2(aiz3, wiz, xB.y);
            fma2(ain0, win, xA.x); fma2(ain1, win, xA.y); fma2(ain2, win, xB.x); fma2(ain3, win, xB.y);
            fma2(ahr0, whr, hA.x); fma2(ahr1, whr, hA.y); fma2(ahr2, whr, hB.x); fma2(ahr3, whr, hB.y);
            fma2(ahz0, whz, hA.x); fma2(ahz1, whz, hA.y); fma2(ahz2, whz, hB.x); fma2(ahz3, whz, hB.y);
            fma2(ahn0, whn, hA.x); fma2(ahn1, whn, hA.y); fma2(ahn2, whn, hB.x); fma2(ahn3, whn, hB.y);
        }
        GRU2(air0, aiz0, ain0, ahr0, ahz0, ahn0, ha.x, ha.y);
        GRU2(air1, aiz1, ain1, ahr1, ahz1, ahn1, ha.z, ha.w);
        GRU2(air2, aiz2, ain2, ahr2, ahz2, ahn2, hb.x, hb.y);
        GRU2(air3, aiz3, ain3, ahr3, ahz3, ahn3, hb.z, hb.w);

        __syncwarp();
        *(float4*)&s_h[(w * 32 + k) * 8]     = ha;
        *(float4*)&s_h[(w * 32 + k) * 8 + 4] = hb;
        __syncwarp();

        // attention score — packed
        U64 tq0 = pk2(wabk), tq1 = tq0, tq2 = tq0, tq3 = tq0;
#pragma unroll 4
        for (int m = 0; m < 32; m++) {
            ulonglong2 hA = *(const ulonglong2*)&s_h[(w * 32 + m) * 8];
            ulonglong2 hB = *(const ulonglong2*)&s_h[(w * 32 + m) * 8 + 4];
            U64 wv2 = pk2(s_wa[m * 32 + k]);
            fma2(tq0, wv2, hA.x); fma2(tq1, wv2, hA.y);
            fma2(tq2, wv2, hB.x); fma2(tq3, wv2, hB.y);
        }
        float4 ta, tb;
        upk(tq0, ta.x, ta.y); upk(tq1, ta.z, ta.w);
        upk(tq2, tb.x, tb.y); upk(tq3, tb.z, tb.w);
        ta.x = tanh_f(ta.x) * vk; ta.y = tanh_f(ta.y) * vk;
        ta.z = tanh_f(ta.z) * vk; ta.w = tanh_f(ta.w) * vk;
        tb.x = tanh_f(tb.x) * vk; tb.y = tanh_f(tb.y) * vk;
        tb.z = tanh_f(tb.z) * vk; tb.w = tanh_f(tb.w) * vk;
        RED4(ta)
        RED4(tb)
        {
            float4 nm;
            nm.x = fmaxf(Ma.x, ta.x); nm.y = fmaxf(Ma.y, ta.y);
            nm.z = fmaxf(Ma.z, ta.z); nm.w = fmaxf(Ma.w, ta.w);
            float f0x = __expf(Ma.x - nm.x), f0y = __expf(Ma.y - nm.y);
            float f0z = __expf(Ma.z - nm.z), f0w = __expf(Ma.w - nm.w);
            float px = __expf(ta.x - nm.x), py = __expf(ta.y - nm.y);
            float pz = __expf(ta.z - nm.z), pw = __expf(ta.w - nm.w);
            Sa.x = Sa.x * f0x + px; Sa.y = Sa.y * f0y + py;
            Sa.z = Sa.z * f0z + pz; Sa.w = Sa.w * f0w + pw;
            pacca.x = pacca.x * f0x + px * ha.x;
            pacca.y = pacca.y * f0y + py * ha.y;
            pacca.z = pacca.z * f0z + pz * ha.z;
            pacca.w = pacca.w * f0w + pw * ha.w;
            Ma = nm;
        }
        {
            float4 nm;
            nm.x = fmaxf(Mb.x, tb.x); nm.y = fmaxf(Mb.y, tb.y);
            nm.z = fmaxf(Mb.z, tb.z); nm.w = fmaxf(Mb.w, tb.w);
            float f0x = __expf(Mb.x - nm.x), f0y = __expf(Mb.y - nm.y);
            float f0z = __expf(Mb.z - nm.z), f0w = __expf(Mb.w - nm.w);
            float px = __expf(tb.x - nm.x), py = __expf(tb.y - nm.y);
            float pz = __expf(tb.z - nm.z), pw = __expf(tb.w - nm.w);
            Sb.x = Sb.x * f0x + px; Sb.y = Sb.y * f0y + py;
            Sb.z = Sb.z * f0z + pz; Sb.w = Sb.w * f0w + pw;
            paccb.x = paccb.x * f0x + px * hb.x;
            paccb.y = paccb.y * f0y + py * hb.y;
            paccb.z = paccb.z * f0z + pz * hb.z;
            paccb.w = paccb.w * f0w + pw * hb.w;
            Mb = nm;
        }
    }
    g_pat[i][j0 + 0][k] = pacca.x / Sa.x;
    g_pat[i][j0 + 1][k] = pacca.y / Sa.y;
    g_pat[i][j0 + 2][k] = pacca.z / Sa.z;
    g_pat[i][j0 + 3][k] = pacca.w / Sa.w;
    g_pat[i][j0 + 4][k] = paccb.x / Sb.x;
    g_pat[i][j0 + 5][k] = paccb.y / Sb.y;
    g_pat[i][j0 + 6][k] = paccb.z / Sb.z;
    g_pat[i][j0 + 7][k] = paccb.w / Sb.w;
}

// ---------------- phase 2: q/k/v + layer softmax -> context -----------------
__global__ void __launch_bounds__(256)
k_ctx(const float* __restrict__ wq1, const float* __restrict__ wq1b,
      const float* __restrict__ wq2, const float* __restrict__ wq2b,
      const float* __restrict__ wk, const float* __restrict__ wkb,
      const float* __restrict__ wv, const float* __restrict__ wvb,
      float* __restrict__ out) {
    __shared__ float s_wq1[1024];
    __shared__ float s_wq2[1024];
    __shared__ float s_wkT[1024];
    __shared__ float s_wv[1024];

    int tid = threadIdx.x, i = blockIdx.x, jb = blockIdx.y;
    int w = tid >> 5, k = tid & 31;
    int j0 = jb * 32 + w * 4;

    for (int idx = tid; idx < 1024; idx += 256) {
        int p = idx >> 5, e = idx & 31;
        s_wq1[idx] = wq1[idx];
        s_wq2[idx] = wq2[idx];
        s_wv[idx]  = wv[idx];
        s_wkT[idx] = wk[e * 32 + p];
    }
    float wq1bk = wq1b[k], wq2bk = wq2b[k], wkbk = wkb[k], wvbk = wvb[k];
    __syncthreads();

    float4 pat;
    pat.x = g_pat[i][j0 + 0][k];
    pat.y = g_pat[i][j0 + 1][k];
    pat.z = g_pat[i][j0 + 2][k];
    pat.w = g_pat[i][j0 + 3][k];

    float4 t1 = set4(wq1bk);
#pragma unroll 4
    for (int m = 0; m < 32; m++) {
        float4 pm = shfl4(pat, m);
        float wv_ = s_wq1[m * 32 + k];
        FMA4V(t1, wv_, pm)
    }
    t1.x = fmaxf(t1.x, 0.f); t1.y = fmaxf(t1.y, 0.f);
    t1.z = fmaxf(t1.z, 0.f); t1.w = fmaxf(t1.w, 0.f);

    float4 q4 = set4(wq2bk);
#pragma unroll 4
    for (int m = 0; m < 32; m++) {
        float4 tm = shfl4(t1, m);
        float wv_ = s_wq2[m * 32 + k];
        FMA4V(q4, wv_, tm)
    }

    float4 qk4 = set4(0.f);
#pragma unroll 4
    for (int p = 0; p < 32; p++) {
        float4 qm = shfl4(q4, p);
        float wv_ = s_wkT[p * 32 + k];
        FMA4V(qk4, wv_, qm)
    }
    float4 qb4;
    qb4.x = q4.x * wkbk; qb4.y = q4.y * wkbk; qb4.z = q4.z * wkbk; qb4.w = q4.w * wkbk;
    RED4(qb4)

    float4 sacc = set4(0.f), M4 = set4(-1e30f), S4 = set4(0.f);
#pragma unroll 1
    for (int l = 0; l < 6; l++) {
        float4 x4;
        x4.x = g_X[l][i][j0 + 0][k];
        x4.y = g_X[l][i][j0 + 1][k];
        x4.z = g_X[l][i][j0 + 2][k];
        x4.w = g_X[l][i][j0 + 3][k];

        float4 s4;
        s4.x = qk4.x * x4.x; s4.y = qk4.y * x4.y; s4.z = qk4.z * x4.z; s4.w = qk4.w * x4.w;
        RED4(s4)
        s4.x = (s4.x + qb4.x) * 0.17677669529663687f;
        s4.y = (s4.y + qb4.y) * 0.17677669529663687f;
        s4.z = (s4.z + qb4.z) * 0.17677669529663687f;
        s4.w = (s4.w + qb4.w) * 0.17677669529663687f;

        float4 nm4;
        nm4.x = fmaxf(M4.x, s4.x); nm4.y = fmaxf(M4.y, s4.y);
        nm4.z = fmaxf(M4.z, s4.z); nm4.w = fmaxf(M4.w, s4.w);
        float f0x = __expf(M4.x - nm4.x), f0y = __expf(M4.y - nm4.y);
        float f0z = __expf(M4.z - nm4.z), f0w = __expf(M4.w - nm4.w);
        float px = __expf(s4.x - nm4.x), py = __expf(s4.y - nm4.y);
        float pz = __expf(s4.z - nm4.z), pw = __expf(s4.w - nm4.w);
        S4.x = S4.x * f0x + px; S4.y = S4.y * f0y + py;
        S4.z = S4.z * f0z + pz; S4.w = S4.w * f0w + pw;
        sacc.x = sacc.x * f0x + px * x4.x;
        sacc.y = sacc.y * f0y + py * x4.y;
        sacc.z = sacc.z * f0z + pz * x4.z;
        sacc.w = sacc.w * f0w + pw * x4.w;
        M4 = nm4;
    }
    sacc.x /= S4.x; sacc.y /= S4.y; sacc.z /= S4.z; sacc.w /= S4.w;

    float4 c4 = set4(wvbk);
#pragma unroll 4
    for (int p = 0; p < 32; p++) {
        float4 sm4 = shfl4(sacc, p);
        float wv_ = s_wv[p * 32 + k];
        FMA4V(c4, wv_, sm4)
    }
    out[((size_t)i * NN + j0 + 0) * KK + k] = c4.x;
    out[((size_t)i * NN + j0 + 1) * KK + k] = c4.y;
    out[((size_t)i * NN + j0 + 2) * KK + k] = c4.z;
    out[((size_t)i * NN + j0 + 3) * KK + k] = c4.w;
}

// ---------------- host ------------------------------------------------------
extern "C" void kernel_launch(void* const* d_in, const int* in_sizes, int n_in,
                              void* d_out, int out_size) {
    const float* f1   = (const float*)d_in[0];
    const float* f2   = (const float*)d_in[1];
    const float* l0w1 = (const float*)d_in[2];
    const float* l0b1 = (const float*)d_in[3];
    const float* l0w2 = (const float*)d_in[4];
    const float* l0b2 = (const float*)d_in[5];
    const float* geps = (const float*)d_in[6];
    const float* gw1  = (const float*)d_in[7];
    const float* gb1  = (const float*)d_in[8];
    const float* gw2  = (const float*)d_in[9];
    const float* gb2  = (const float*)d_in[10];
    const float* gga  = (const float*)d_in[11];
    const float* gbe  = (const float*)d_in[12];
    const float* ged  = (const float*)d_in[13];
    const float* wih  = (const float*)d_in[14];
    const float* whh  = (const float*)d_in[15];
    const float* bih  = (const float*)d_in[16];
    const float* bhh  = (const float*)d_in[17];
    const float* waw  = (const float*)d_in[18];
    const float* wab  = (const float*)d_in[19];
    const float* vat  = (const float*)d_in[20];
    const float* wq1  = (const float*)d_in[21];
    const float* wq1b = (const float*)d_in[22];
    const float* wq2  = (const float*)d_in[23];
    const float* wq2b = (const float*)d_in[24];
    const float* wk   = (const float*)d_in[25];
    const float* wkb  = (const float*)d_in[26];
    const float* wv   = (const float*)d_in[27];
    const float* wvb  = (const float*)d_in[28];
    const int*   e1   = (const int*)d_in[29];
    const int*   e2   = (const int*)d_in[30];
    float* out = (float*)d_out;

    cudaFuncSetAttribute(k_pat, cudaFuncAttributeMaxDynamicSharedMemorySize, KP_SMEM * 4);

    k_deg<<<dim3(96, 2), 128>>>(e1, e2);
    k_lin0<<<dim3(24, 2), 256>>>(f1, f2, l0w1, l0b1, l0w2, l0b2);
    for (int l = 0; l < 5; l++) {
        k_agg<<<1728, 256>>>(e1, e2);
        k_mlp<<<dim3(24, 2), 256>>>(gw1, gb1, gw2, gb2, geps, l);
        k_bn<<<dim3(64, 2), 384>>>(gga, gbe, l);
    }
    k_A<<<dim3(6, 24), 256>>>(ged);
    k_h2T<<<576, 256>>>();
    k_pat<<<dim3(384, 6), 256, KP_SMEM * 4>>>(wih, whh, bih, bhh, waw, wab, vat);
    k_ctx<<<dim3(384, 12), 256>>>(wq1, wq1b, wq2, wq2b, wk, wkb, wv, wvb, out);
}